// round 1
// baseline (speedup 1.0000x reference)
#include <cuda_runtime.h>
#include <math.h>

#define N_TOK 8192
#define D_DIM 1024
#define BW    512      // band storage row stride
#define BVAL  499      // valid band entries per row (2*249+1)

// ---------------- scratch (static device arrays, no allocation) -------------
__device__ float g_Q[(size_t)N_TOK * D_DIM];
__device__ float g_K[(size_t)N_TOK * D_DIM];
__device__ float g_V[(size_t)N_TOK * D_DIM];
__device__ float g_Y[(size_t)N_TOK * D_DIM];
__device__ float g_A[(size_t)N_TOK * BW];     // band logits -> softmax weights

// ---------------- C = A @ B^T, A:[M,K] row-major, B:[Nc,K] row-major --------
// 128x128x16 tile, 256 threads, 8x8 per thread.
__global__ __launch_bounds__(256)
void gemm_abt(const float* __restrict__ A, const float* __restrict__ B,
              float* __restrict__ C, int M, int Nc, int Kd, float scale)
{
    __shared__ float As[16][128];
    __shared__ float Bs[16][128];

    const int tid = threadIdx.x;
    const int bm = blockIdx.y * 128;
    const int bn = blockIdx.x * 128;
    const int tx = tid & 15;          // 0..15
    const int ty = tid >> 4;          // 0..15
    const int lr  = tid >> 2;         // 0..63
    const int lk4 = (tid & 3) * 4;    // 0,4,8,12

    float acc[8][8];
#pragma unroll
    for (int r = 0; r < 8; r++)
#pragma unroll
        for (int c = 0; c < 8; c++) acc[r][c] = 0.f;

    for (int k0 = 0; k0 < Kd; k0 += 16) {
#pragma unroll
        for (int h = 0; h < 2; h++) {
            int r = lr + h * 64;
            float4 va = *(const float4*)(A + (size_t)(bm + r) * Kd + k0 + lk4);
            As[lk4 + 0][r] = va.x; As[lk4 + 1][r] = va.y;
            As[lk4 + 2][r] = va.z; As[lk4 + 3][r] = va.w;
            float4 vb = *(const float4*)(B + (size_t)(bn + r) * Kd + k0 + lk4);
            Bs[lk4 + 0][r] = vb.x; Bs[lk4 + 1][r] = vb.y;
            Bs[lk4 + 2][r] = vb.z; Bs[lk4 + 3][r] = vb.w;
        }
        __syncthreads();
#pragma unroll
        for (int k = 0; k < 16; k++) {
            float a[8], b[8];
            *(float4*)(a)     = *(const float4*)&As[k][ty * 8];
            *(float4*)(a + 4) = *(const float4*)&As[k][ty * 8 + 4];
            *(float4*)(b)     = *(const float4*)&Bs[k][tx * 8];
            *(float4*)(b + 4) = *(const float4*)&Bs[k][tx * 8 + 4];
#pragma unroll
            for (int r = 0; r < 8; r++)
#pragma unroll
                for (int c = 0; c < 8; c++) acc[r][c] += a[r] * b[c];
        }
        __syncthreads();
    }

#pragma unroll
    for (int r = 0; r < 8; r++) {
        float4 v0, v1;
        v0.x = acc[r][0] * scale; v0.y = acc[r][1] * scale;
        v0.z = acc[r][2] * scale; v0.w = acc[r][3] * scale;
        v1.x = acc[r][4] * scale; v1.y = acc[r][5] * scale;
        v1.z = acc[r][6] * scale; v1.w = acc[r][7] * scale;
        float* cp = C + (size_t)(bm + ty * 8 + r) * Nc + bn + tx * 8;
        *(float4*)(cp)     = v0;
        *(float4*)(cp + 4) = v1;
    }
}

// ---------------- banded logits: Aband[i][j-i+249] = Q[i]·K[j] --------------
// 64x64 tile, tile column offsets -4..+4 around the diagonal block.
__global__ __launch_bounds__(256)
void banded_logits(const float* __restrict__ Q, const float* __restrict__ K,
                   float* __restrict__ Aband)
{
    const int i0 = blockIdx.y * 64;
    const int j0 = i0 + ((int)blockIdx.x - 4) * 64;
    if (j0 + 64 <= 0 || j0 >= N_TOK) return;

    __shared__ float Qs[16][64];
    __shared__ float Ks[16][64];
    const int tid = threadIdx.x;
    const int tx = tid & 15, ty = tid >> 4;
    const int lr = tid >> 2;            // 0..63
    const int lk4 = (tid & 3) * 4;

    float acc[4][4];
#pragma unroll
    for (int r = 0; r < 4; r++)
#pragma unroll
        for (int c = 0; c < 4; c++) acc[r][c] = 0.f;

    for (int k0 = 0; k0 < D_DIM; k0 += 16) {
        float4 q = *(const float4*)(Q + (size_t)(i0 + lr) * D_DIM + k0 + lk4);
        Qs[lk4 + 0][lr] = q.x; Qs[lk4 + 1][lr] = q.y;
        Qs[lk4 + 2][lr] = q.z; Qs[lk4 + 3][lr] = q.w;
        int jr = j0 + lr;
        float4 kv = make_float4(0.f, 0.f, 0.f, 0.f);
        if (jr >= 0 && jr < N_TOK)
            kv = *(const float4*)(K + (size_t)jr * D_DIM + k0 + lk4);
        Ks[lk4 + 0][lr] = kv.x; Ks[lk4 + 1][lr] = kv.y;
        Ks[lk4 + 2][lr] = kv.z; Ks[lk4 + 3][lr] = kv.w;
        __syncthreads();
#pragma unroll
        for (int k = 0; k < 16; k++) {
            float a[4], b[4];
            *(float4*)a = *(const float4*)&Qs[k][ty * 4];
            *(float4*)b = *(const float4*)&Ks[k][tx * 4];
#pragma unroll
            for (int r = 0; r < 4; r++)
#pragma unroll
                for (int c = 0; c < 4; c++) acc[r][c] += a[r] * b[c];
        }
        __syncthreads();
    }

#pragma unroll
    for (int r = 0; r < 4; r++) {
        int i = i0 + ty * 4 + r;
#pragma unroll
        for (int c = 0; c < 4; c++) {
            int j = j0 + tx * 4 + c;
            int t = j - i + 249;
            if ((unsigned)j < (unsigned)N_TOK && (unsigned)t < (unsigned)BVAL)
                Aband[(size_t)i * BW + t] = acc[r][c];
        }
    }
}

// ---------------- per-row band softmax (in place) ---------------------------
__global__ __launch_bounds__(128)
void band_softmax(float* __restrict__ Aband)
{
    const int i = blockIdx.x;
    const int tlo = max(0, 249 - i);
    const int thi = min(BVAL - 1, N_TOK - 1 - i + 249);
    const int tid = threadIdx.x;
    float* row = Aband + (size_t)i * BW;

    __shared__ float red[128];

    float mx = -INFINITY;
    for (int t = tlo + tid; t <= thi; t += 128) mx = fmaxf(mx, row[t]);
    red[tid] = mx; __syncthreads();
    for (int s = 64; s > 0; s >>= 1) {
        if (tid < s) red[tid] = fmaxf(red[tid], red[tid + s]);
        __syncthreads();
    }
    mx = red[0]; __syncthreads();

    float sum = 0.f;
    for (int t = tlo + tid; t <= thi; t += 128) {
        float e = __expf(row[t] - mx);
        row[t] = e;
        sum += e;
    }
    red[tid] = sum; __syncthreads();
    for (int s = 64; s > 0; s >>= 1) {
        if (tid < s) red[tid] += red[tid + s];
        __syncthreads();
    }
    float inv = 1.f / red[0]; __syncthreads();

    for (int t = tlo + tid; t <= thi; t += 128) row[t] *= inv;
}

// ---------------- Y = A^T @ V (banded): Y[j,d] = sum_i A[i,j]*V[i,d] --------
// tile: 64 j-rows x 64 d-cols, i chunks of 16 over [j0-256, j0+320)
__global__ __launch_bounds__(256)
void banded_av(const float* __restrict__ Aband, const float* __restrict__ V,
               float* __restrict__ Y)
{
    const int j0 = blockIdx.y * 64;
    const int d0 = blockIdx.x * 64;
    __shared__ float Ats[16][64];   // [i-chunk][j]
    __shared__ float Vs[16][64];    // [i-chunk][d]

    const int tid = threadIdx.x;
    const int tx = tid & 15, ty = tid >> 4;
    const int kk  = tid >> 4;         // 0..15 (i within chunk)
    const int lb4 = (tid & 15) * 4;   // 0..60 (j or d, x4)

    float acc[4][4];
#pragma unroll
    for (int r = 0; r < 4; r++)
#pragma unroll
        for (int c = 0; c < 4; c++) acc[r][c] = 0.f;

    for (int ic = j0 - 256; ic < j0 + 320; ic += 16) {
        int i = ic + kk;
        bool iok = (i >= 0 && i < N_TOK);
#pragma unroll
        for (int q = 0; q < 4; q++) {
            int j = j0 + lb4 + q;
            int t = j - i + 249;
            float v = 0.f;
            if (iok && (unsigned)t < (unsigned)BVAL)
                v = Aband[(size_t)i * BW + t];
            Ats[kk][lb4 + q] = v;
        }
        float4 vv = make_float4(0.f, 0.f, 0.f, 0.f);
        if (iok) vv = *(const float4*)(V + (size_t)i * D_DIM + d0 + lb4);
        *(float4*)&Vs[kk][lb4] = vv;
        __syncthreads();
#pragma unroll
        for (int k = 0; k < 16; k++) {
            float a[4], b[4];
            *(float4*)a = *(const float4*)&Ats[k][ty * 4];
            *(float4*)b = *(const float4*)&Vs[k][tx * 4];
#pragma unroll
            for (int r = 0; r < 4; r++)
#pragma unroll
                for (int c = 0; c < 4; c++) acc[r][c] += a[r] * b[c];
        }
        __syncthreads();
    }

#pragma unroll
    for (int r = 0; r < 4; r++) {
        float4 v;
        v.x = acc[r][0]; v.y = acc[r][1]; v.z = acc[r][2]; v.w = acc[r][3];
        *(float4*)(Y + (size_t)(j0 + ty * 4 + r) * D_DIM + d0 + tx * 4) = v;
    }
}

// ---------------- expand band weights to dense att output -------------------
__global__ __launch_bounds__(256)
void write_att(const float* __restrict__ Aband, float* __restrict__ att)
{
    const int i = blockIdx.y;
    const int j = (blockIdx.x * 256 + threadIdx.x) * 4;
    float4 o;
    float r[4];
#pragma unroll
    for (int q = 0; q < 4; q++) {
        int t = j + q - i + 249;
        r[q] = ((unsigned)t < (unsigned)BVAL) ? Aband[(size_t)i * BW + t] : 0.f;
    }
    o.x = r[0]; o.y = r[1]; o.z = r[2]; o.w = r[3];
    *(float4*)(att + (size_t)i * N_TOK + j) = o;
}

// ---------------------------------------------------------------------------
extern "C" void kernel_launch(void* const* d_in, const int* in_sizes, int n_in,
                              void* d_out, int out_size)
{
    const float* x  = (const float*)d_in[0];
    const float* Wq = (const float*)d_in[1];
    const float* Wk = (const float*)d_in[2];
    const float* Wv = (const float*)d_in[3];
    const float* Wo = (const float*)d_in[4];

    float *pQ, *pK, *pV, *pY, *pA;
    cudaGetSymbolAddress((void**)&pQ, g_Q);
    cudaGetSymbolAddress((void**)&pK, g_K);
    cudaGetSymbolAddress((void**)&pV, g_V);
    cudaGetSymbolAddress((void**)&pY, g_Y);
    cudaGetSymbolAddress((void**)&pA, g_A);

    const long ND = (long)N_TOK * D_DIM;
    const long NN = (long)N_TOK * N_TOK;

    float* out = (float*)d_out;
    float* yout = out;
    float* attout = nullptr;
    if ((long)out_size >= ND + NN) {
        yout = out;
        attout = out + ND;
    } else if ((long)out_size == NN) {
        yout = pQ;          // y not part of output; dump into scratch
        attout = out;
    } // else: out_size == ND -> y only

    dim3 gproj(D_DIM / 128, N_TOK / 128);
    gemm_abt<<<gproj, 256>>>(x, Wq, pQ, N_TOK, D_DIM, D_DIM, 0.06f);
    gemm_abt<<<gproj, 256>>>(x, Wk, pK, N_TOK, D_DIM, D_DIM, 1.0f);
    gemm_abt<<<gproj, 256>>>(x, Wv, pV, N_TOK, D_DIM, D_DIM, 1.0f);

    banded_logits<<<dim3(9, N_TOK / 64), 256>>>(pQ, pK, pA);
    band_softmax<<<N_TOK, 128>>>(pA);
    banded_av<<<dim3(D_DIM / 64, N_TOK / 64), 256>>>(pA, pV, pY);

    gemm_abt<<<gproj, 256>>>(pY, Wo, yout, N_TOK, D_DIM, D_DIM, 1.0f);

    if (attout)
        write_att<<<dim3(N_TOK / 1024, N_TOK), 256>>>(pA, attout);
}

// round 3
// speedup vs baseline: 1.7061x; 1.7061x over previous
#include <cuda_runtime.h>
#include <cuda_bf16.h>
#include <math.h>
#include <stdint.h>

#define N_TOK 8192
#define D_DIM 1024
#define BW    512
#define BVAL  499

// ---------------- scratch (static device arrays, no allocation) -------------
__device__ float g_Q[(size_t)N_TOK * D_DIM];
__device__ float g_K[(size_t)N_TOK * D_DIM];
__device__ float g_V[(size_t)N_TOK * D_DIM];
__device__ float g_Y[(size_t)N_TOK * D_DIM];
__device__ float g_A[(size_t)N_TOK * BW];

__device__ __nv_bfloat16 g_xhi[(size_t)N_TOK * D_DIM];
__device__ __nv_bfloat16 g_xlo[(size_t)N_TOK * D_DIM];
__device__ __nv_bfloat16 g_yhi[(size_t)N_TOK * D_DIM];
__device__ __nv_bfloat16 g_ylo[(size_t)N_TOK * D_DIM];
__device__ __nv_bfloat16 g_w[8][(size_t)D_DIM * D_DIM]; // qh,ql,kh,kl,vh,vl,oh,ol

// ======================= helpers ============================================
__device__ __forceinline__ uint32_t smem_u32(const void* p) {
    uint32_t a;
    asm("{ .reg .u64 t; cvta.to.shared.u64 t, %1; cvt.u32.u64 %0, t; }"
        : "=r"(a) : "l"(p));
    return a;
}
__device__ __forceinline__ void cp16(uint32_t dst, const void* src) {
    asm volatile("cp.async.cg.shared.global [%0], [%1], 16;" :: "r"(dst), "l"(src));
}
__device__ __forceinline__ void cp_commit() {
    asm volatile("cp.async.commit_group;" ::: "memory");
}
template <int NN_> __device__ __forceinline__ void cp_wait() {
    asm volatile("cp.async.wait_group %0;" :: "n"(NN_) : "memory");
}
__device__ __forceinline__ void ldm_x4(uint32_t& r0, uint32_t& r1, uint32_t& r2,
                                       uint32_t& r3, uint32_t addr) {
    asm volatile("ldmatrix.sync.aligned.m8n8.x4.shared.b16 {%0,%1,%2,%3}, [%4];"
                 : "=r"(r0), "=r"(r1), "=r"(r2), "=r"(r3) : "r"(addr));
}
__device__ __forceinline__ void mma_bf16(float* c, uint32_t a0, uint32_t a1,
                                         uint32_t a2, uint32_t a3,
                                         uint32_t b0, uint32_t b1) {
    asm volatile(
        "mma.sync.aligned.m16n8k16.row.col.f32.bf16.bf16.f32 "
        "{%0,%1,%2,%3}, {%4,%5,%6,%7}, {%8,%9}, {%0,%1,%2,%3};"
        : "+f"(c[0]), "+f"(c[1]), "+f"(c[2]), "+f"(c[3])
        : "r"(a0), "r"(a1), "r"(a2), "r"(a3), "r"(b0), "r"(b1));
}

// ======================= split fp32 -> bf16 hi/lo ===========================
__global__ __launch_bounds__(256)
void split_bf16(const float* __restrict__ s, __nv_bfloat16* __restrict__ hi,
                __nv_bfloat16* __restrict__ lo, int n4)
{
    int i = blockIdx.x * 256 + threadIdx.x;
    if (i >= n4) return;
    float4 v = ((const float4*)s)[i];
    __nv_bfloat16 h0 = __float2bfloat16(v.x);
    __nv_bfloat16 h1 = __float2bfloat16(v.y);
    __nv_bfloat16 h2 = __float2bfloat16(v.z);
    __nv_bfloat16 h3 = __float2bfloat16(v.w);
    __nv_bfloat16 l0 = __float2bfloat16(v.x - __bfloat162float(h0));
    __nv_bfloat16 l1 = __float2bfloat16(v.y - __bfloat162float(h1));
    __nv_bfloat16 l2 = __float2bfloat16(v.z - __bfloat162float(h2));
    __nv_bfloat16 l3 = __float2bfloat16(v.w - __bfloat162float(h3));
    __nv_bfloat162* hp = (__nv_bfloat162*)hi;
    __nv_bfloat162* lp = (__nv_bfloat162*)lo;
    hp[2 * i]     = __halves2bfloat162(h0, h1);
    hp[2 * i + 1] = __halves2bfloat162(h2, h3);
    lp[2 * i]     = __halves2bfloat162(l0, l1);
    lp[2 * i + 1] = __halves2bfloat162(l2, l3);
}

// ======================= mma.sync GEMM: C = A @ B^T =========================
// A: [M,1024] bf16 hi/lo, B: [1024,1024] bf16 hi/lo (row-major n x k), C fp32.
// CTA 128x128, K-chunk 32, 3-stage cp.async pipeline, 8 warps (2M x 4N),
// warp tile 64x32. 3 passes: hi*hi + hi*lo + lo*hi.
#define TCK    32
#define NCH    (D_DIM / TCK)      // 32
#define ROWB   80                 // padded row stride in bytes (32 bf16 + 8 pad)
#define TILEB  (128 * ROWB)       // 10240 B
#define STAGEB (4 * TILEB)        // Ahi, Alo, Bhi, Blo
#define NSTAGE 3

__global__ __launch_bounds__(256, 1)
void mma_gemm(const __nv_bfloat16* __restrict__ Ahi, const __nv_bfloat16* __restrict__ Alo,
              const __nv_bfloat16* __restrict__ Bhi, const __nv_bfloat16* __restrict__ Blo,
              float* __restrict__ C, float scale)
{
    extern __shared__ __align__(128) char smem[];
    const uint32_t sbase = smem_u32(smem);
    const int tid  = threadIdx.x;
    const int lane = tid & 31;
    const int wid  = tid >> 5;
    const int wm   = wid & 1;       // 0..1 -> M offset 64*wm
    const int wn   = wid >> 1;      // 0..3 -> N offset 32*wn
    const int i0 = blockIdx.y * 128;
    const int j0 = blockIdx.x * 128;

    const __nv_bfloat16* srcs[4] = {
        Ahi + (size_t)i0 * D_DIM, Alo + (size_t)i0 * D_DIM,
        Bhi + (size_t)j0 * D_DIM, Blo + (size_t)j0 * D_DIM};

    auto load_chunk = [&](int c, int st) {
        const uint32_t sb = sbase + st * STAGEB;
        const int k0 = c * TCK;
#pragma unroll
        for (int t = 0; t < 4; t++) {
            const __nv_bfloat16* base = srcs[t] + k0;
            uint32_t dstb = sb + t * TILEB;
#pragma unroll
            for (int h = 0; h < 2; h++) {
                int idx = tid + h * 256;            // 0..511
                int r = idx >> 2, ck = idx & 3;
                cp16(dstb + r * ROWB + ck * 16, base + (size_t)r * D_DIM + ck * 8);
            }
        }
    };

    // per-thread ldmatrix offsets
    const int a_row = lane & 15;                 // row within m16 tile
    const int a_kg  = (lane >> 4) * 8;           // k offset 0/8
    const int b_row = (lane & 7) + ((lane >> 4) << 3);   // row within n16 group
    const int b_kg  = ((lane >> 3) & 1) * 8;

    float acc[4][4][4];
#pragma unroll
    for (int mi = 0; mi < 4; mi++)
#pragma unroll
        for (int ni = 0; ni < 4; ni++)
#pragma unroll
            for (int q = 0; q < 4; q++) acc[mi][ni][q] = 0.f;

    load_chunk(0, 0); cp_commit();
    load_chunk(1, 1); cp_commit();
    load_chunk(2, 2); cp_commit();

    for (int c = 0; c < NCH; c++) {
        cp_wait<NSTAGE - 1>();
        __syncthreads();

        const uint32_t sb = sbase + (c % NSTAGE) * STAGEB;
        const uint32_t aH = sb;
        const uint32_t aL = sb + TILEB;
        const uint32_t bH = sb + 2 * TILEB;
        const uint32_t bL = sb + 3 * TILEB;

#pragma unroll
        for (int s = 0; s < 2; s++) {
            const int kc = s * 16;
            uint32_t ah[4][4], al[4][4], bh[2][4], bl[2][4];
#pragma unroll
            for (int mi = 0; mi < 4; mi++) {
                uint32_t ra = (wm * 64 + mi * 16 + a_row) * ROWB + (kc + a_kg) * 2;
                ldm_x4(ah[mi][0], ah[mi][1], ah[mi][2], ah[mi][3], aH + ra);
                ldm_x4(al[mi][0], al[mi][1], al[mi][2], al[mi][3], aL + ra);
            }
#pragma unroll
            for (int g = 0; g < 2; g++) {
                uint32_t rb = (wn * 32 + g * 16 + b_row) * ROWB + (kc + b_kg) * 2;
                ldm_x4(bh[g][0], bh[g][1], bh[g][2], bh[g][3], bH + rb);
                ldm_x4(bl[g][0], bl[g][1], bl[g][2], bl[g][3], bL + rb);
            }
#pragma unroll
            for (int mi = 0; mi < 4; mi++)
#pragma unroll
                for (int ni = 0; ni < 4; ni++) {
                    uint32_t b0h = bh[ni >> 1][(ni & 1) * 2];
                    uint32_t b1h = bh[ni >> 1][(ni & 1) * 2 + 1];
                    uint32_t b0l = bl[ni >> 1][(ni & 1) * 2];
                    uint32_t b1l = bl[ni >> 1][(ni & 1) * 2 + 1];
                    mma_bf16(acc[mi][ni], ah[mi][0], ah[mi][1], ah[mi][2], ah[mi][3], b0h, b1h);
                    mma_bf16(acc[mi][ni], ah[mi][0], ah[mi][1], ah[mi][2], ah[mi][3], b0l, b1l);
                    mma_bf16(acc[mi][ni], al[mi][0], al[mi][1], al[mi][2], al[mi][3], b0h, b1h);
                }
        }

        __syncthreads();
        if (c + NSTAGE < NCH) load_chunk(c + NSTAGE, c % NSTAGE);
        cp_commit();   // real or empty group, keeps wait_group accounting simple
    }

    // epilogue: direct fp32 stores
    const int rbase = i0 + wm * 64;
    const int cbase = j0 + wn * 32;
#pragma unroll
    for (int mi = 0; mi < 4; mi++) {
        int r0 = rbase + mi * 16 + (lane >> 2);
#pragma unroll
        for (int ni = 0; ni < 4; ni++) {
            int cc = cbase + ni * 8 + (lane & 3) * 2;
            float2 v0 = make_float2(acc[mi][ni][0] * scale, acc[mi][ni][1] * scale);
            float2 v1 = make_float2(acc[mi][ni][2] * scale, acc[mi][ni][3] * scale);
            *(float2*)(C + (size_t)r0 * D_DIM + cc) = v0;
            *(float2*)(C + (size_t)(r0 + 8) * D_DIM + cc) = v1;
        }
    }
}

// ---------------- banded logits: Aband[i][j-i+249] = Q[i]·K[j] --------------
__global__ __launch_bounds__(256)
void banded_logits(const float* __restrict__ Q, const float* __restrict__ K,
                   float* __restrict__ Aband)
{
    const int i0 = blockIdx.y * 64;
    const int j0 = i0 + ((int)blockIdx.x - 4) * 64;
    if (j0 + 64 <= 0 || j0 >= N_TOK) return;

    __shared__ float Qs[16][64];
    __shared__ float Ks[16][64];
    const int tid = threadIdx.x;
    const int tx = tid & 15, ty = tid >> 4;
    const int lr = tid >> 2;
    const int lk4 = (tid & 3) * 4;

    float acc[4][4];
#pragma unroll
    for (int r = 0; r < 4; r++)
#pragma unroll
        for (int c = 0; c < 4; c++) acc[r][c] = 0.f;

    for (int k0 = 0; k0 < D_DIM; k0 += 16) {
        float4 q = *(const float4*)(Q + (size_t)(i0 + lr) * D_DIM + k0 + lk4);
        Qs[lk4 + 0][lr] = q.x; Qs[lk4 + 1][lr] = q.y;
        Qs[lk4 + 2][lr] = q.z; Qs[lk4 + 3][lr] = q.w;
        int jr = j0 + lr;
        float4 kv = make_float4(0.f, 0.f, 0.f, 0.f);
        if (jr >= 0 && jr < N_TOK)
            kv = *(const float4*)(K + (size_t)jr * D_DIM + k0 + lk4);
        Ks[lk4 + 0][lr] = kv.x; Ks[lk4 + 1][lr] = kv.y;
        Ks[lk4 + 2][lr] = kv.z; Ks[lk4 + 3][lr] = kv.w;
        __syncthreads();
#pragma unroll
        for (int k = 0; k < 16; k++) {
            float a[4], b[4];
            *(float4*)a = *(const float4*)&Qs[k][ty * 4];
            *(float4*)b = *(const float4*)&Ks[k][tx * 4];
#pragma unroll
            for (int r = 0; r < 4; r++)
#pragma unroll
                for (int c = 0; c < 4; c++) acc[r][c] += a[r] * b[c];
        }
        __syncthreads();
    }

#pragma unroll
    for (int r = 0; r < 4; r++) {
        int i = i0 + ty * 4 + r;
#pragma unroll
        for (int c = 0; c < 4; c++) {
            int j = j0 + tx * 4 + c;
            int t = j - i + 249;
            if ((unsigned)j < (unsigned)N_TOK && (unsigned)t < (unsigned)BVAL)
                Aband[(size_t)i * BW + t] = acc[r][c];
        }
    }
}

// ---------------- per-row band softmax (in place) ---------------------------
__global__ __launch_bounds__(128)
void band_softmax(float* __restrict__ Aband)
{
    const int i = blockIdx.x;
    const int tlo = max(0, 249 - i);
    const int thi = min(BVAL - 1, N_TOK - 1 - i + 249);
    const int tid = threadIdx.x;
    float* row = Aband + (size_t)i * BW;

    __shared__ float red[128];

    float mx = -INFINITY;
    for (int t = tlo + tid; t <= thi; t += 128) mx = fmaxf(mx, row[t]);
    red[tid] = mx; __syncthreads();
    for (int s = 64; s > 0; s >>= 1) {
        if (tid < s) red[tid] = fmaxf(red[tid], red[tid + s]);
        __syncthreads();
    }
    mx = red[0]; __syncthreads();

    float sum = 0.f;
    for (int t = tlo + tid; t <= thi; t += 128) {
        float e = __expf(row[t] - mx);
        row[t] = e;
        sum += e;
    }
    red[tid] = sum; __syncthreads();
    for (int s = 64; s > 0; s >>= 1) {
        if (tid < s) red[tid] += red[tid + s];
        __syncthreads();
    }
    float inv = 1.f / red[0]; __syncthreads();

    for (int t = tlo + tid; t <= thi; t += 128) row[t] *= inv;
}

// ---------------- Y = A^T @ V (banded) --------------------------------------
__global__ __launch_bounds__(256)
void banded_av(const float* __restrict__ Aband, const float* __restrict__ V,
               float* __restrict__ Y)
{
    const int j0 = blockIdx.y * 64;
    const int d0 = blockIdx.x * 64;
    __shared__ float Ats[16][64];
    __shared__ float Vs[16][64];

    const int tid = threadIdx.x;
    const int tx = tid & 15, ty = tid >> 4;
    const int kk  = tid >> 4;
    const int lb4 = (tid & 15) * 4;

    float acc[4][4];
#pragma unroll
    for (int r = 0; r < 4; r++)
#pragma unroll
        for (int c = 0; c < 4; c++) acc[r][c] = 0.f;

    for (int ic = j0 - 256; ic < j0 + 320; ic += 16) {
        int i = ic + kk;
        bool iok = (i >= 0 && i < N_TOK);
#pragma unroll
        for (int q = 0; q < 4; q++) {
            int j = j0 + lb4 + q;
            int t = j - i + 249;
            float v = 0.f;
            if (iok && (unsigned)t < (unsigned)BVAL)
                v = Aband[(size_t)i * BW + t];
            Ats[kk][lb4 + q] = v;
        }
        float4 vv = make_float4(0.f, 0.f, 0.f, 0.f);
        if (iok) vv = *(const float4*)(V + (size_t)i * D_DIM + d0 + lb4);
        *(float4*)&Vs[kk][lb4] = vv;
        __syncthreads();
#pragma unroll
        for (int k = 0; k < 16; k++) {
            float a[4], b[4];
            *(float4*)a = *(const float4*)&Ats[k][ty * 4];
            *(float4*)b = *(const float4*)&Vs[k][tx * 4];
#pragma unroll
            for (int r = 0; r < 4; r++)
#pragma unroll
                for (int c = 0; c < 4; c++) acc[r][c] += a[r] * b[c];
        }
        __syncthreads();
    }

#pragma unroll
    for (int r = 0; r < 4; r++) {
        float4 v;
        v.x = acc[r][0]; v.y = acc[r][1]; v.z = acc[r][2]; v.w = acc[r][3];
        *(float4*)(Y + (size_t)(j0 + ty * 4 + r) * D_DIM + d0 + tx * 4) = v;
    }
}

// ---------------- expand band weights to dense att output -------------------
__global__ __launch_bounds__(256)
void write_att(const float* __restrict__ Aband, float* __restrict__ att)
{
    const int i = blockIdx.y;
    const int j = (blockIdx.x * 256 + threadIdx.x) * 4;
    float4 o;
    float r[4];
#pragma unroll
    for (int q = 0; q < 4; q++) {
        int t = j + q - i + 249;
        r[q] = ((unsigned)t < (unsigned)BVAL) ? Aband[(size_t)i * BW + t] : 0.f;
    }
    o.x = r[0]; o.y = r[1]; o.z = r[2]; o.w = r[3];
    *(float4*)(att + (size_t)i * N_TOK + j) = o;
}

// ---------------------------------------------------------------------------
extern "C" void kernel_launch(void* const* d_in, const int* in_sizes, int n_in,
                              void* d_out, int out_size)
{
    const float* x  = (const float*)d_in[0];
    const float* Wq = (const float*)d_in[1];
    const float* Wk = (const float*)d_in[2];
    const float* Wv = (const float*)d_in[3];
    const float* Wo = (const float*)d_in[4];

    float *pQ, *pK, *pV, *pY, *pA;
    cudaGetSymbolAddress((void**)&pQ, g_Q);
    cudaGetSymbolAddress((void**)&pK, g_K);
    cudaGetSymbolAddress((void**)&pV, g_V);
    cudaGetSymbolAddress((void**)&pY, g_Y);
    cudaGetSymbolAddress((void**)&pA, g_A);

    __nv_bfloat16 *xhi, *xlo, *yhi, *ylo, *wsp;
    cudaGetSymbolAddress((void**)&xhi, g_xhi);
    cudaGetSymbolAddress((void**)&xlo, g_xlo);
    cudaGetSymbolAddress((void**)&yhi, g_yhi);
    cudaGetSymbolAddress((void**)&ylo, g_ylo);
    cudaGetSymbolAddress((void**)&wsp, g_w);
    const size_t WSZ = (size_t)D_DIM * D_DIM;
    __nv_bfloat16* wq_h = wsp + 0 * WSZ; __nv_bfloat16* wq_l = wsp + 1 * WSZ;
    __nv_bfloat16* wk_h = wsp + 2 * WSZ; __nv_bfloat16* wk_l = wsp + 3 * WSZ;
    __nv_bfloat16* wv_h = wsp + 4 * WSZ; __nv_bfloat16* wv_l = wsp + 5 * WSZ;
    __nv_bfloat16* wo_h = wsp + 6 * WSZ; __nv_bfloat16* wo_l = wsp + 7 * WSZ;

    const long ND = (long)N_TOK * D_DIM;
    const long NN = (long)N_TOK * N_TOK;

    float* out = (float*)d_out;
    float* yout = out;
    float* attout = nullptr;
    if ((long)out_size >= ND + NN) {
        yout = out;
        attout = out + ND;
    } else if ((long)out_size == NN) {
        yout = pQ;
        attout = out;
    }

    const int SMEM_GEMM = NSTAGE * STAGEB;     // 3 * 40960 = 122880
    cudaFuncSetAttribute(mma_gemm, cudaFuncAttributeMaxDynamicSharedMemorySize, SMEM_GEMM);

    // split inputs to bf16 hi/lo
    split_bf16<<<(N_TOK * D_DIM / 4 + 255) / 256, 256>>>(x, xhi, xlo, N_TOK * D_DIM / 4);
    split_bf16<<<(D_DIM * D_DIM / 4 + 255) / 256, 256>>>(Wq, wq_h, wq_l, D_DIM * D_DIM / 4);
    split_bf16<<<(D_DIM * D_DIM / 4 + 255) / 256, 256>>>(Wk, wk_h, wk_l, D_DIM * D_DIM / 4);
    split_bf16<<<(D_DIM * D_DIM / 4 + 255) / 256, 256>>>(Wv, wv_h, wv_l, D_DIM * D_DIM / 4);
    split_bf16<<<(D_DIM * D_DIM / 4 + 255) / 256, 256>>>(Wo, wo_h, wo_l, D_DIM * D_DIM / 4);

    dim3 gg(D_DIM / 128, N_TOK / 128);
    mma_gemm<<<gg, 256, SMEM_GEMM>>>(xhi, xlo, wq_h, wq_l, pQ, 0.06f);
    mma_gemm<<<gg, 256, SMEM_GEMM>>>(xhi, xlo, wk_h, wk_l, pK, 1.0f);
    mma_gemm<<<gg, 256, SMEM_GEMM>>>(xhi, xlo, wv_h, wv_l, pV, 1.0f);

    banded_logits<<<dim3(9, N_TOK / 64), 256>>>(pQ, pK, pA);
    band_softmax<<<N_TOK, 128>>>(pA);
    banded_av<<<dim3(D_DIM / 64, N_TOK / 64), 256>>>(pA, pV, pY);

    split_bf16<<<(N_TOK * D_DIM / 4 + 255) / 256, 256>>>(pY, yhi, ylo, N_TOK * D_DIM / 4);
    mma_gemm<<<gg, 256, SMEM_GEMM>>>(yhi, ylo, wo_h, wo_l, yout, 1.0f);

    if (attout)
        write_att<<<dim3(N_TOK / 1024, N_TOK), 256>>>(pA, attout);
}

// round 6
// speedup vs baseline: 2.1688x; 1.2712x over previous
#include <cuda_runtime.h>
#include <cuda_bf16.h>
#include <math.h>
#include <stdint.h>

#define N_TOK 8192
#define D_DIM 1024
#define BW    512
#define BVAL  499

typedef __nv_bfloat16 bf16;

// ---------------- scratch (static device arrays, no allocation) -------------
__device__ float g_A[(size_t)N_TOK * BW];        // band logits -> weights (fp32)
__device__ float g_Ydump[(size_t)N_TOK * D_DIM]; // y sink when only att requested

__device__ bf16 g_xhi[(size_t)N_TOK * D_DIM];
__device__ bf16 g_xlo[(size_t)N_TOK * D_DIM];
__device__ bf16 g_Qh[(size_t)N_TOK * D_DIM];
__device__ bf16 g_Ql[(size_t)N_TOK * D_DIM];
__device__ bf16 g_Kh[(size_t)N_TOK * D_DIM];
__device__ bf16 g_Kl[(size_t)N_TOK * D_DIM];
__device__ bf16 g_Vh[(size_t)N_TOK * D_DIM];
__device__ bf16 g_Vl[(size_t)N_TOK * D_DIM];
__device__ bf16 g_Yh[(size_t)N_TOK * D_DIM];
__device__ bf16 g_Yl[(size_t)N_TOK * D_DIM];
__device__ bf16 g_w[8][(size_t)D_DIM * D_DIM];   // qh,ql,kh,kl,vh,vl,oh,ol
__device__ bf16 g_Abt_h[(size_t)N_TOK * 640];    // [jb][128][640]
__device__ bf16 g_Abt_l[(size_t)N_TOK * 640];

// ======================= helpers ============================================
__device__ __forceinline__ uint32_t smem_u32(const void* p) {
    uint32_t a;
    asm("{ .reg .u64 t; cvta.to.shared.u64 t, %1; cvt.u32.u64 %0, t; }"
        : "=r"(a) : "l"(p));
    return a;
}
__device__ __forceinline__ void cp16(uint32_t dst, const void* src) {
    asm volatile("cp.async.cg.shared.global [%0], [%1], 16;" :: "r"(dst), "l"(src));
}
__device__ __forceinline__ void cp_commit() {
    asm volatile("cp.async.commit_group;" ::: "memory");
}
template <int NN_> __device__ __forceinline__ void cp_wait() {
    asm volatile("cp.async.wait_group %0;" :: "n"(NN_) : "memory");
}
__device__ __forceinline__ void ldm_x4(uint32_t& r0, uint32_t& r1, uint32_t& r2,
                                       uint32_t& r3, uint32_t addr) {
    asm volatile("ldmatrix.sync.aligned.m8n8.x4.shared.b16 {%0,%1,%2,%3}, [%4];"
                 : "=r"(r0), "=r"(r1), "=r"(r2), "=r"(r3) : "r"(addr));
}
__device__ __forceinline__ void ldm_x4t(uint32_t& r0, uint32_t& r1, uint32_t& r2,
                                        uint32_t& r3, uint32_t addr) {
    asm volatile("ldmatrix.sync.aligned.m8n8.x4.trans.shared.b16 {%0,%1,%2,%3}, [%4];"
                 : "=r"(r0), "=r"(r1), "=r"(r2), "=r"(r3) : "r"(addr));
}
__device__ __forceinline__ void mma_bf16(float* c, uint32_t a0, uint32_t a1,
                                         uint32_t a2, uint32_t a3,
                                         uint32_t b0, uint32_t b1) {
    asm volatile(
        "mma.sync.aligned.m16n8k16.row.col.f32.bf16.bf16.f32 "
        "{%0,%1,%2,%3}, {%4,%5,%6,%7}, {%8,%9}, {%0,%1,%2,%3};"
        : "+f"(c[0]), "+f"(c[1]), "+f"(c[2]), "+f"(c[3])
        : "r"(a0), "r"(a1), "r"(a2), "r"(a3), "r"(b0), "r"(b1));
}

// ======================= split fp32 -> bf16 hi/lo ===========================
__global__ __launch_bounds__(256)
void split_bf16(const float* __restrict__ s, bf16* __restrict__ hi,
                bf16* __restrict__ lo, int n4)
{
    int i = blockIdx.x * 256 + threadIdx.x;
    if (i >= n4) return;
    float4 v = ((const float4*)s)[i];
    bf16 h0 = __float2bfloat16(v.x);
    bf16 h1 = __float2bfloat16(v.y);
    bf16 h2 = __float2bfloat16(v.z);
    bf16 h3 = __float2bfloat16(v.w);
    bf16 l0 = __float2bfloat16(v.x - __bfloat162float(h0));
    bf16 l1 = __float2bfloat16(v.y - __bfloat162float(h1));
    bf16 l2 = __float2bfloat16(v.z - __bfloat162float(h2));
    bf16 l3 = __float2bfloat16(v.w - __bfloat162float(h3));
    __nv_bfloat162* hp = (__nv_bfloat162*)hi;
    __nv_bfloat162* lp = (__nv_bfloat162*)lo;
    hp[2 * i]     = __halves2bfloat162(h0, h1);
    hp[2 * i + 1] = __halves2bfloat162(h2, h3);
    lp[2 * i]     = __halves2bfloat162(l0, l1);
    lp[2 * i + 1] = __halves2bfloat162(l2, l3);
}

// ======================= GEMM tile constants ================================
#define TCK    32
#define NCH    (D_DIM / TCK)      // 32
#define ROWB   80                 // padded A/B row stride (32 bf16 + pad)
#define TILEB  (128 * ROWB)       // 10240
#define STAGEB (4 * TILEB)
#define NSTAGE 3

// lane->fragment maps. NOTE: A and B (non-trans) maps DIFFER.
#define DECL_FRAG_IDX                                        \
    const int lane = tid & 31;                               \
    const int wid  = tid >> 5;                               \
    const int wm   = wid & 1;                                \
    const int wn   = wid >> 1;                               \
    const int a_row = lane & 15;                             \
    const int a_kg  = (lane >> 4) * 8;                       \
    const int b_row = (lane & 7) + ((lane >> 4) << 3);       \
    const int b_kg  = ((lane >> 3) & 1) * 8;

// ======================= dense GEMM, bf16 hi/lo split output ================
__global__ __launch_bounds__(256, 1)
void mma_gemm_bf16out(const bf16* __restrict__ Ahi, const bf16* __restrict__ Alo,
                      const bf16* __restrict__ Bhi, const bf16* __restrict__ Blo,
                      bf16* __restrict__ Chi, bf16* __restrict__ Clo, float scale)
{
    extern __shared__ __align__(128) char smem[];
    const uint32_t sbase = smem_u32(smem);
    const int tid = threadIdx.x;
    DECL_FRAG_IDX
    const int i0 = blockIdx.y * 128;
    const int j0 = blockIdx.x * 128;

    const bf16* srcs[4] = {Ahi + (size_t)i0 * D_DIM, Alo + (size_t)i0 * D_DIM,
                           Bhi + (size_t)j0 * D_DIM, Blo + (size_t)j0 * D_DIM};

    auto load_chunk = [&](int c, int st) {
        const uint32_t sb = sbase + st * STAGEB;
        const int k0 = c * TCK;
#pragma unroll
        for (int t = 0; t < 4; t++) {
            const bf16* base = srcs[t] + k0;
            uint32_t dstb = sb + t * TILEB;
#pragma unroll
            for (int h = 0; h < 2; h++) {
                int idx = tid + h * 256;
                int r = idx >> 2, ck = idx & 3;
                cp16(dstb + r * ROWB + ck * 16, base + (size_t)r * D_DIM + ck * 8);
            }
        }
    };

    float acc[4][4][4];
#pragma unroll
    for (int mi = 0; mi < 4; mi++)
#pragma unroll
        for (int ni = 0; ni < 4; ni++)
#pragma unroll
            for (int q = 0; q < 4; q++) acc[mi][ni][q] = 0.f;

    load_chunk(0, 0); cp_commit();
    load_chunk(1, 1); cp_commit();
    load_chunk(2, 2); cp_commit();

    for (int c = 0; c < NCH; c++) {
        cp_wait<NSTAGE - 1>();
        __syncthreads();
        const uint32_t sb = sbase + (c % NSTAGE) * STAGEB;
#pragma unroll
        for (int s = 0; s < 2; s++) {
            const int kc = s * 16;
            uint32_t ah[4][4], al[4][4], bh[2][4], bl[2][4];
#pragma unroll
            for (int mi = 0; mi < 4; mi++) {
                uint32_t ra = (wm * 64 + mi * 16 + a_row) * ROWB + (kc + a_kg) * 2;
                ldm_x4(ah[mi][0], ah[mi][1], ah[mi][2], ah[mi][3], sb + ra);
                ldm_x4(al[mi][0], al[mi][1], al[mi][2], al[mi][3], sb + TILEB + ra);
            }
#pragma unroll
            for (int g = 0; g < 2; g++) {
                uint32_t rb = (wn * 32 + g * 16 + b_row) * ROWB + (kc + b_kg) * 2;
                ldm_x4(bh[g][0], bh[g][1], bh[g][2], bh[g][3], sb + 2 * TILEB + rb);
                ldm_x4(bl[g][0], bl[g][1], bl[g][2], bl[g][3], sb + 3 * TILEB + rb);
            }
#pragma unroll
            for (int mi = 0; mi < 4; mi++)
#pragma unroll
                for (int ni = 0; ni < 4; ni++) {
                    uint32_t b0h = bh[ni >> 1][(ni & 1) * 2], b1h = bh[ni >> 1][(ni & 1) * 2 + 1];
                    uint32_t b0l = bl[ni >> 1][(ni & 1) * 2], b1l = bl[ni >> 1][(ni & 1) * 2 + 1];
                    mma_bf16(acc[mi][ni], ah[mi][0], ah[mi][1], ah[mi][2], ah[mi][3], b0h, b1h);
                    mma_bf16(acc[mi][ni], ah[mi][0], ah[mi][1], ah[mi][2], ah[mi][3], b0l, b1l);
                    mma_bf16(acc[mi][ni], al[mi][0], al[mi][1], al[mi][2], al[mi][3], b0h, b1h);
                }
        }
        __syncthreads();
        if (c + NSTAGE < NCH) load_chunk(c + NSTAGE, c % NSTAGE);
        cp_commit();
    }

    const int rbase = i0 + wm * 64;
    const int cbase = j0 + wn * 32;
#pragma unroll
    for (int mi = 0; mi < 4; mi++) {
        int r0 = rbase + mi * 16 + (lane >> 2);
#pragma unroll
        for (int ni = 0; ni < 4; ni++) {
            int cc = cbase + ni * 8 + (lane & 3) * 2;
#pragma unroll
            for (int hrow = 0; hrow < 2; hrow++) {
                float v0 = acc[mi][ni][hrow * 2 + 0] * scale;
                float v1 = acc[mi][ni][hrow * 2 + 1] * scale;
                bf16 h0 = __float2bfloat16(v0);
                bf16 h1 = __float2bfloat16(v1);
                bf16 l0 = __float2bfloat16(v0 - __bfloat162float(h0));
                bf16 l1 = __float2bfloat16(v1 - __bfloat162float(h1));
                size_t off = (size_t)(r0 + hrow * 8) * D_DIM + cc;
                *(__nv_bfloat162*)(Chi + off) = __halves2bfloat162(h0, h1);
                *(__nv_bfloat162*)(Clo + off) = __halves2bfloat162(l0, l1);
            }
        }
    }
}

// ======================= dense GEMM, fp32 output (final) ====================
__global__ __launch_bounds__(256, 1)
void mma_gemm_f32out(const bf16* __restrict__ Ahi, const bf16* __restrict__ Alo,
                     const bf16* __restrict__ Bhi, const bf16* __restrict__ Blo,
                     float* __restrict__ C)
{
    extern __shared__ __align__(128) char smem[];
    const uint32_t sbase = smem_u32(smem);
    const int tid = threadIdx.x;
    DECL_FRAG_IDX
    const int i0 = blockIdx.y * 128;
    const int j0 = blockIdx.x * 128;

    const bf16* srcs[4] = {Ahi + (size_t)i0 * D_DIM, Alo + (size_t)i0 * D_DIM,
                           Bhi + (size_t)j0 * D_DIM, Blo + (size_t)j0 * D_DIM};

    auto load_chunk = [&](int c, int st) {
        const uint32_t sb = sbase + st * STAGEB;
        const int k0 = c * TCK;
#pragma unroll
        for (int t = 0; t < 4; t++) {
            const bf16* base = srcs[t] + k0;
            uint32_t dstb = sb + t * TILEB;
#pragma unroll
            for (int h = 0; h < 2; h++) {
                int idx = tid + h * 256;
                int r = idx >> 2, ck = idx & 3;
                cp16(dstb + r * ROWB + ck * 16, base + (size_t)r * D_DIM + ck * 8);
            }
        }
    };

    float acc[4][4][4];
#pragma unroll
    for (int mi = 0; mi < 4; mi++)
#pragma unroll
        for (int ni = 0; ni < 4; ni++)
#pragma unroll
            for (int q = 0; q < 4; q++) acc[mi][ni][q] = 0.f;

    load_chunk(0, 0); cp_commit();
    load_chunk(1, 1); cp_commit();
    load_chunk(2, 2); cp_commit();

    for (int c = 0; c < NCH; c++) {
        cp_wait<NSTAGE - 1>();
        __syncthreads();
        const uint32_t sb = sbase + (c % NSTAGE) * STAGEB;
#pragma unroll
        for (int s = 0; s < 2; s++) {
            const int kc = s * 16;
            uint32_t ah[4][4], al[4][4], bh[2][4], bl[2][4];
#pragma unroll
            for (int mi = 0; mi < 4; mi++) {
                uint32_t ra = (wm * 64 + mi * 16 + a_row) * ROWB + (kc + a_kg) * 2;
                ldm_x4(ah[mi][0], ah[mi][1], ah[mi][2], ah[mi][3], sb + ra);
                ldm_x4(al[mi][0], al[mi][1], al[mi][2], al[mi][3], sb + TILEB + ra);
            }
#pragma unroll
            for (int g = 0; g < 2; g++) {
                uint32_t rb = (wn * 32 + g * 16 + b_row) * ROWB + (kc + b_kg) * 2;
                ldm_x4(bh[g][0], bh[g][1], bh[g][2], bh[g][3], sb + 2 * TILEB + rb);
                ldm_x4(bl[g][0], bl[g][1], bl[g][2], bl[g][3], sb + 3 * TILEB + rb);
            }
#pragma unroll
            for (int mi = 0; mi < 4; mi++)
#pragma unroll
                for (int ni = 0; ni < 4; ni++) {
                    uint32_t b0h = bh[ni >> 1][(ni & 1) * 2], b1h = bh[ni >> 1][(ni & 1) * 2 + 1];
                    uint32_t b0l = bl[ni >> 1][(ni & 1) * 2], b1l = bl[ni >> 1][(ni & 1) * 2 + 1];
                    mma_bf16(acc[mi][ni], ah[mi][0], ah[mi][1], ah[mi][2], ah[mi][3], b0h, b1h);
                    mma_bf16(acc[mi][ni], ah[mi][0], ah[mi][1], ah[mi][2], ah[mi][3], b0l, b1l);
                    mma_bf16(acc[mi][ni], al[mi][0], al[mi][1], al[mi][2], al[mi][3], b0h, b1h);
                }
        }
        __syncthreads();
        if (c + NSTAGE < NCH) load_chunk(c + NSTAGE, c % NSTAGE);
        cp_commit();
    }

    const int rbase = i0 + wm * 64;
    const int cbase = j0 + wn * 32;
#pragma unroll
    for (int mi = 0; mi < 4; mi++) {
        int r0 = rbase + mi * 16 + (lane >> 2);
#pragma unroll
        for (int ni = 0; ni < 4; ni++) {
            int cc = cbase + ni * 8 + (lane & 3) * 2;
            *(float2*)(C + (size_t)r0 * D_DIM + cc) =
                make_float2(acc[mi][ni][0], acc[mi][ni][1]);
            *(float2*)(C + (size_t)(r0 + 8) * D_DIM + cc) =
                make_float2(acc[mi][ni][2], acc[mi][ni][3]);
        }
    }
}

// ======================= banded logits via mma ==============================
// grid (5, 64): i0 = by*128, j0 = i0 + (bx-2)*128. Band-masked store to Aband.
__global__ __launch_bounds__(256, 1)
void banded_logits_mma(const bf16* __restrict__ Qh, const bf16* __restrict__ Ql,
                       const bf16* __restrict__ Kh, const bf16* __restrict__ Kl,
                       float* __restrict__ Aband)
{
    extern __shared__ __align__(128) char smem[];
    const uint32_t sbase = smem_u32(smem);
    const int tid = threadIdx.x;
    DECL_FRAG_IDX
    const int i0 = blockIdx.y * 128;
    const int j0 = i0 + ((int)blockIdx.x - 2) * 128;

    auto load_chunk = [&](int c, int st) {
        const uint32_t sb = sbase + st * STAGEB;
        const int k0 = c * TCK;
#pragma unroll
        for (int t = 0; t < 2; t++) {            // A = Q rows (always valid)
            const bf16* base = (t ? Ql : Qh) + k0;
            uint32_t dstb = sb + t * TILEB;
#pragma unroll
            for (int h = 0; h < 2; h++) {
                int idx = tid + h * 256;
                int r = idx >> 2, ck = idx & 3;
                cp16(dstb + r * ROWB + ck * 16, base + (size_t)(i0 + r) * D_DIM + ck * 8);
            }
        }
#pragma unroll
        for (int t = 0; t < 2; t++) {            // B = K rows (clamped)
            const bf16* base = (t ? Kl : Kh) + k0;
            uint32_t dstb = sb + (2 + t) * TILEB;
#pragma unroll
            for (int h = 0; h < 2; h++) {
                int idx = tid + h * 256;
                int r = idx >> 2, ck = idx & 3;
                int jr = j0 + r;
                jr = jr < 0 ? 0 : (jr >= N_TOK ? N_TOK - 1 : jr);
                cp16(dstb + r * ROWB + ck * 16, base + (size_t)jr * D_DIM + ck * 8);
            }
        }
    };

    float acc[4][4][4];
#pragma unroll
    for (int mi = 0; mi < 4; mi++)
#pragma unroll
        for (int ni = 0; ni < 4; ni++)
#pragma unroll
            for (int q = 0; q < 4; q++) acc[mi][ni][q] = 0.f;

    load_chunk(0, 0); cp_commit();
    load_chunk(1, 1); cp_commit();
    load_chunk(2, 2); cp_commit();

    for (int c = 0; c < NCH; c++) {
        cp_wait<NSTAGE - 1>();
        __syncthreads();
        const uint32_t sb = sbase + (c % NSTAGE) * STAGEB;
#pragma unroll
        for (int s = 0; s < 2; s++) {
            const int kc = s * 16;
            uint32_t ah[4][4], al[4][4], bh[2][4], bl[2][4];
#pragma unroll
            for (int mi = 0; mi < 4; mi++) {
                uint32_t ra = (wm * 64 + mi * 16 + a_row) * ROWB + (kc + a_kg) * 2;
                ldm_x4(ah[mi][0], ah[mi][1], ah[mi][2], ah[mi][3], sb + ra);
                ldm_x4(al[mi][0], al[mi][1], al[mi][2], al[mi][3], sb + TILEB + ra);
            }
#pragma unroll
            for (int g = 0; g < 2; g++) {
                uint32_t rb = (wn * 32 + g * 16 + b_row) * ROWB + (kc + b_kg) * 2;
                ldm_x4(bh[g][0], bh[g][1], bh[g][2], bh[g][3], sb + 2 * TILEB + rb);
                ldm_x4(bl[g][0], bl[g][1], bl[g][2], bl[g][3], sb + 3 * TILEB + rb);
            }
#pragma unroll
            for (int mi = 0; mi < 4; mi++)
#pragma unroll
                for (int ni = 0; ni < 4; ni++) {
                    uint32_t b0h = bh[ni >> 1][(ni & 1) * 2], b1h = bh[ni >> 1][(ni & 1) * 2 + 1];
                    uint32_t b0l = bl[ni >> 1][(ni & 1) * 2], b1l = bl[ni >> 1][(ni & 1) * 2 + 1];
                    mma_bf16(acc[mi][ni], ah[mi][0], ah[mi][1], ah[mi][2], ah[mi][3], b0h, b1h);
                    mma_bf16(acc[mi][ni], ah[mi][0], ah[mi][1], ah[mi][2], ah[mi][3], b0l, b1l);
                    mma_bf16(acc[mi][ni], al[mi][0], al[mi][1], al[mi][2], al[mi][3], b0h, b1h);
                }
        }
        __syncthreads();
        if (c + NSTAGE < NCH) load_chunk(c + NSTAGE, c % NSTAGE);
        cp_commit();
    }

    const int rbase = i0 + wm * 64;
    const int cbase = j0 + wn * 32;
#pragma unroll
    for (int mi = 0; mi < 4; mi++) {
#pragma unroll
        for (int hrow = 0; hrow < 2; hrow++) {
            int i = rbase + mi * 16 + (lane >> 2) + hrow * 8;
#pragma unroll
            for (int ni = 0; ni < 4; ni++) {
#pragma unroll
                for (int q = 0; q < 2; q++) {
                    int j = cbase + ni * 8 + (lane & 3) * 2 + q;
                    int t = j - i + 249;
                    if ((unsigned)j < (unsigned)N_TOK && (unsigned)t < (unsigned)BVAL)
                        Aband[(size_t)i * BW + t] = acc[mi][ni][hrow * 2 + q];
                }
            }
        }
    }
}

// ---------------- per-row band softmax (in place) ---------------------------
__global__ __launch_bounds__(128)
void band_softmax(float* __restrict__ Aband)
{
    const int i = blockIdx.x;
    const int tlo = max(0, 249 - i);
    const int thi = min(BVAL - 1, N_TOK - 1 - i + 249);
    const int tid = threadIdx.x;
    float* row = Aband + (size_t)i * BW;

    __shared__ float red[128];

    float mx = -INFINITY;
    for (int t = tlo + tid; t <= thi; t += 128) mx = fmaxf(mx, row[t]);
    red[tid] = mx; __syncthreads();
    for (int s = 64; s > 0; s >>= 1) {
        if (tid < s) red[tid] = fmaxf(red[tid], red[tid + s]);
        __syncthreads();
    }
    mx = red[0]; __syncthreads();

    float sum = 0.f;
    for (int t = tlo + tid; t <= thi; t += 128) {
        float e = __expf(row[t] - mx);
        row[t] = e;
        sum += e;
    }
    red[tid] = sum; __syncthreads();
    for (int s = 64; s > 0; s >>= 1) {
        if (tid < s) red[tid] += red[tid + s];
        __syncthreads();
    }
    float inv = 1.f / red[0]; __syncthreads();

    for (int t = tlo + tid; t <= thi; t += 128) row[t] *= inv;
}

// -------- transpose band weights into per-block K-aligned bf16 hi/lo --------
// Abt[jb][jl][ii] = A[i, jb*128+jl] where i = jb*128 - 256 + ii (0 outside)
__global__ __launch_bounds__(256)
void band_transpose(const float* __restrict__ Aband,
                    bf16* __restrict__ Abt_h, bf16* __restrict__ Abt_l)
{
    const int jb = blockIdx.z;
    const int j0l = blockIdx.y * 64;
    const int ii0 = blockIdx.x * 64;
    const int j0 = jb * 128 + j0l;
    const int ibase = jb * 128 - 256 + ii0;
    const int tid = threadIdx.x;

    __shared__ float ts[64][65];

    for (int e = tid; e < 64 * 64; e += 256) {
        int r = e >> 6, jc = e & 63;
        int i = ibase + r, j = j0 + jc;
        int t = j - i + 249;
        float v = 0.f;
        if ((unsigned)i < (unsigned)N_TOK && (unsigned)t < (unsigned)BVAL)
            v = Aband[(size_t)i * BW + t];
        ts[r][jc] = v;
    }
    __syncthreads();

    for (int e = tid; e < 64 * 64; e += 256) {
        int jc = e >> 6, r = e & 63;
        float v = ts[r][jc];
        bf16 h = __float2bfloat16(v);
        bf16 l = __float2bfloat16(v - __bfloat162float(h));
        size_t off = ((size_t)jb * 128 + j0l + jc) * 640 + ii0 + r;
        Abt_h[off] = h;
        Abt_l[off] = l;
    }
}

// ======================= banded A^T@V via mma ===============================
// C[j, d] = sum_ii Abt[jb][j][ii] * V[jb*128-256+ii][d]
#define AVK    640
#define NCH2   (AVK / TCK)        // 20
#define ROWVB  272                // 128 bf16 + pad
#define VTILEB (32 * ROWVB)       // 8704
#define AVSTAGE (2 * TILEB + 2 * VTILEB)  // 37888

__global__ __launch_bounds__(256, 1)
void banded_av_mma(const bf16* __restrict__ Abt_h, const bf16* __restrict__ Abt_l,
                   const bf16* __restrict__ Vh, const bf16* __restrict__ Vl,
                   bf16* __restrict__ Yh, bf16* __restrict__ Yl)
{
    extern __shared__ __align__(128) char smem[];
    const uint32_t sbase = smem_u32(smem);
    const int tid = threadIdx.x;
    DECL_FRAG_IDX
    const int jb = blockIdx.y;
    const int d0 = blockIdx.x * 128;
    const int jbase = jb * 128 - 256;

    const bf16* Ab[2] = {Abt_h + (size_t)jb * 128 * 640, Abt_l + (size_t)jb * 128 * 640};
    const bf16* Vb[2] = {Vh, Vl};

    auto load_chunk = [&](int c, int st) {
        const uint32_t sb = sbase + st * AVSTAGE;
        const int k0 = c * TCK;
#pragma unroll
        for (int t = 0; t < 2; t++) {            // A tiles: 128 rows x 32 k
            const bf16* base = Ab[t] + k0;
            uint32_t dstb = sb + t * TILEB;
#pragma unroll
            for (int h = 0; h < 2; h++) {
                int idx = tid + h * 256;
                int r = idx >> 2, ck = idx & 3;
                cp16(dstb + r * ROWB + ck * 16, base + (size_t)r * 640 + ck * 8);
            }
        }
#pragma unroll
        for (int t = 0; t < 2; t++) {            // V tiles: 32 i-rows x 128 d
            const bf16* base = Vb[t] + d0;
            uint32_t dstb = sb + 2 * TILEB + t * VTILEB;
#pragma unroll
            for (int h = 0; h < 2; h++) {
                int idx = tid + h * 256;
                int r = idx >> 4, ck = idx & 15;
                int i = jbase + k0 + r;
                i = i < 0 ? 0 : (i >= N_TOK ? N_TOK - 1 : i);
                cp16(dstb + r * ROWVB + ck * 16, base + (size_t)i * D_DIM + ck * 8);
            }
        }
    };

    float acc[4][4][4];
#pragma unroll
    for (int mi = 0; mi < 4; mi++)
#pragma unroll
        for (int ni = 0; ni < 4; ni++)
#pragma unroll
            for (int q = 0; q < 4; q++) acc[mi][ni][q] = 0.f;

    load_chunk(0, 0); cp_commit();
    load_chunk(1, 1); cp_commit();
    load_chunk(2, 2); cp_commit();

    for (int c = 0; c < NCH2; c++) {
        cp_wait<NSTAGE - 1>();
        __syncthreads();
        const uint32_t sb = sbase + (c % NSTAGE) * AVSTAGE;
#pragma unroll
        for (int s = 0; s < 2; s++) {
            const int kc = s * 16;
            uint32_t ah[4][4], al[4][4], bh[2][4], bl[2][4];
#pragma unroll
            for (int mi = 0; mi < 4; mi++) {
                uint32_t ra = (wm * 64 + mi * 16 + a_row) * ROWB + (kc + a_kg) * 2;
                ldm_x4(ah[mi][0], ah[mi][1], ah[mi][2], ah[mi][3], sb + ra);
                ldm_x4(al[mi][0], al[mi][1], al[mi][2], al[mi][3], sb + TILEB + ra);
            }
#pragma unroll
            for (int g = 0; g < 2; g++) {
                // B via trans ldmatrix: rows = k (i), cols = d
                uint32_t rb = (uint32_t)(kc + (lane & 15)) * ROWVB
                            + (wn * 32 + g * 16 + (lane >> 4) * 8) * 2;
                ldm_x4t(bh[g][0], bh[g][1], bh[g][2], bh[g][3], sb + 2 * TILEB + rb);
                ldm_x4t(bl[g][0], bl[g][1], bl[g][2], bl[g][3], sb + 2 * TILEB + VTILEB + rb);
            }
#pragma unroll
            for (int mi = 0; mi < 4; mi++)
#pragma unroll
                for (int ni = 0; ni < 4; ni++) {
                    uint32_t b0h = bh[ni >> 1][(ni & 1) * 2], b1h = bh[ni >> 1][(ni & 1) * 2 + 1];
                    uint32_t b0l = bl[ni >> 1][(ni & 1) * 2], b1l = bl[ni >> 1][(ni & 1) * 2 + 1];
                    mma_bf16(acc[mi][ni], ah[mi][0], ah[mi][1], ah[mi][2], ah[mi][3], b0h, b1h);
                    mma_bf16(acc[mi][ni], ah[mi][0], ah[mi][1], ah[mi][2], ah[mi][3], b0l, b1l);
                    mma_bf16(acc[mi][ni], al[mi][0], al[mi][1], al[mi][2], al[mi][3], b0h, b1h);
                }
        }
        __syncthreads();
        if (c + NSTAGE < NCH2) load_chunk(c + NSTAGE, c % NSTAGE);
        cp_commit();
    }

    const int rbase = jb * 128 + wm * 64;
    const int cbase = d0 + wn * 32;
#pragma unroll
    for (int mi = 0; mi < 4; mi++) {
        int r0 = rbase + mi * 16 + (lane >> 2);
#pragma unroll
        for (int ni = 0; ni < 4; ni++) {
            int cc = cbase + ni * 8 + (lane & 3) * 2;
#pragma unroll
            for (int hrow = 0; hrow < 2; hrow++) {
                float v0 = acc[mi][ni][hrow * 2 + 0];
                float v1 = acc[mi][ni][hrow * 2 + 1];
                bf16 h0 = __float2bfloat16(v0);
                bf16 h1 = __float2bfloat16(v1);
                bf16 l0 = __float2bfloat16(v0 - __bfloat162float(h0));
                bf16 l1 = __float2bfloat16(v1 - __bfloat162float(h1));
                size_t off = (size_t)(r0 + hrow * 8) * D_DIM + cc;
                *(__nv_bfloat162*)(Yh + off) = __halves2bfloat162(h0, h1);
                *(__nv_bfloat162*)(Yl + off) = __halves2bfloat162(l0, l1);
            }
        }
    }
}

// ---------------- expand band weights to dense att output -------------------
__global__ __launch_bounds__(256)
void write_att(const float* __restrict__ Aband, float* __restrict__ att)
{
    const int i = blockIdx.y;
    const int j = (blockIdx.x * 256 + threadIdx.x) * 4;
    float4 o;
    float r[4];
#pragma unroll
    for (int q = 0; q < 4; q++) {
        int t = j + q - i + 249;
        r[q] = ((unsigned)t < (unsigned)BVAL) ? Aband[(size_t)i * BW + t] : 0.f;
    }
    o.x = r[0]; o.y = r[1]; o.z = r[2]; o.w = r[3];
    *(float4*)(att + (size_t)i * N_TOK + j) = o;
}

// ---------------------------------------------------------------------------
extern "C" void kernel_launch(void* const* d_in, const int* in_sizes, int n_in,
                              void* d_out, int out_size)
{
    const float* x  = (const float*)d_in[0];
    const float* Wq = (const float*)d_in[1];
    const float* Wk = (const float*)d_in[2];
    const float* Wv = (const float*)d_in[3];
    const float* Wo = (const float*)d_in[4];

    float *pA, *pYd;
    cudaGetSymbolAddress((void**)&pA, g_A);
    cudaGetSymbolAddress((void**)&pYd, g_Ydump);

    bf16 *xhi, *xlo, *qh, *ql, *kh, *kl, *vh, *vl, *yh, *yl, *wsp, *abth, *abtl;
    cudaGetSymbolAddress((void**)&xhi, g_xhi);
    cudaGetSymbolAddress((void**)&xlo, g_xlo);
    cudaGetSymbolAddress((void**)&qh, g_Qh);
    cudaGetSymbolAddress((void**)&ql, g_Ql);
    cudaGetSymbolAddress((void**)&kh, g_Kh);
    cudaGetSymbolAddress((void**)&kl, g_Kl);
    cudaGetSymbolAddress((void**)&vh, g_Vh);
    cudaGetSymbolAddress((void**)&vl, g_Vl);
    cudaGetSymbolAddress((void**)&yh, g_Yh);
    cudaGetSymbolAddress((void**)&yl, g_Yl);
    cudaGetSymbolAddress((void**)&wsp, g_w);
    cudaGetSymbolAddress((void**)&abth, g_Abt_h);
    cudaGetSymbolAddress((void**)&abtl, g_Abt_l);

    const size_t WSZ = (size_t)D_DIM * D_DIM;
    bf16* wq_h = wsp + 0 * WSZ; bf16* wq_l = wsp + 1 * WSZ;
    bf16* wk_h = wsp + 2 * WSZ; bf16* wk_l = wsp + 3 * WSZ;
    bf16* wv_h = wsp + 4 * WSZ; bf16* wv_l = wsp + 5 * WSZ;
    bf16* wo_h = wsp + 6 * WSZ; bf16* wo_l = wsp + 7 * WSZ;

    const long ND = (long)N_TOK * D_DIM;
    const long NN = (long)N_TOK * N_TOK;

    float* out = (float*)d_out;
    float* yout = out;
    float* attout = nullptr;
    if ((long)out_size >= ND + NN) {
        yout = out;
        attout = out + ND;
    } else if ((long)out_size == NN) {
        yout = pYd;
        attout = out;
    }

    const int SMEM_GEMM = NSTAGE * STAGEB;      // 122880
    const int SMEM_AV   = NSTAGE * AVSTAGE;     // 113664
    cudaFuncSetAttribute(mma_gemm_bf16out, cudaFuncAttributeMaxDynamicSharedMemorySize, SMEM_GEMM);
    cudaFuncSetAttribute(mma_gemm_f32out, cudaFuncAttributeMaxDynamicSharedMemorySize, SMEM_GEMM);
    cudaFuncSetAttribute(banded_logits_mma, cudaFuncAttributeMaxDynamicSharedMemorySize, SMEM_GEMM);
    cudaFuncSetAttribute(banded_av_mma, cudaFuncAttributeMaxDynamicSharedMemorySize, SMEM_AV);

    // splits
    split_bf16<<<(N_TOK * D_DIM / 4 + 255) / 256, 256>>>(x, xhi, xlo, N_TOK * D_DIM / 4);
    split_bf16<<<(D_DIM * D_DIM / 4 + 255) / 256, 256>>>(Wq, wq_h, wq_l, D_DIM * D_DIM / 4);
    split_bf16<<<(D_DIM * D_DIM / 4 + 255) / 256, 256>>>(Wk, wk_h, wk_l, D_DIM * D_DIM / 4);
    split_bf16<<<(D_DIM * D_DIM / 4 + 255) / 256, 256>>>(Wv, wv_h, wv_l, D_DIM * D_DIM / 4);
    split_bf16<<<(D_DIM * D_DIM / 4 + 255) / 256, 256>>>(Wo, wo_h, wo_l, D_DIM * D_DIM / 4);

    // projections (write bf16 hi/lo directly; Q pre-scaled)
    dim3 gg(D_DIM / 128, N_TOK / 128);
    mma_gemm_bf16out<<<gg, 256, SMEM_GEMM>>>(xhi, xlo, wq_h, wq_l, qh, ql, 0.06f);
    mma_gemm_bf16out<<<gg, 256, SMEM_GEMM>>>(xhi, xlo, wk_h, wk_l, kh, kl, 1.0f);
    mma_gemm_bf16out<<<gg, 256, SMEM_GEMM>>>(xhi, xlo, wv_h, wv_l, vh, vl, 1.0f);

    // banded attention
    banded_logits_mma<<<dim3(5, N_TOK / 128), 256, SMEM_GEMM>>>(qh, ql, kh, kl, pA);
    band_softmax<<<N_TOK, 128>>>(pA);
    band_transpose<<<dim3(10, 2, N_TOK / 128), 256>>>(pA, abth, abtl);
    banded_av_mma<<<dim3(D_DIM / 128, N_TOK / 128), 256, SMEM_AV>>>(abth, abtl, vh, vl, yh, yl);

    // output projection
    mma_gemm_f32out<<<gg, 256, SMEM_GEMM>>>(yh, yl, wo_h, wo_l, yout);

    if (attout)
        write_att<<<dim3(N_TOK / 1024, N_TOK), 256>>>(pA, attout);
}

// round 7
// speedup vs baseline: 2.5971x; 1.1975x over previous
#include <cuda_runtime.h>
#include <cuda_bf16.h>
#include <math.h>
#include <stdint.h>

#define N_TOK 8192
#define D_DIM 1024
#define BW    512
#define BVAL  499

typedef __nv_bfloat16 bf16;

// ---------------- scratch (static device arrays, no allocation) -------------
__device__ float g_A[(size_t)N_TOK * BW];
__device__ float g_Ydump[(size_t)N_TOK * D_DIM];

__device__ bf16 g_xhi[(size_t)N_TOK * D_DIM];
__device__ bf16 g_xlo[(size_t)N_TOK * D_DIM];
__device__ bf16 g_Ph[3][(size_t)N_TOK * D_DIM];   // Q,K,V hi
__device__ bf16 g_Pl[3][(size_t)N_TOK * D_DIM];   // Q,K,V lo
__device__ bf16 g_Yh[(size_t)N_TOK * D_DIM];
__device__ bf16 g_Yl[(size_t)N_TOK * D_DIM];
__device__ bf16 g_w[8][(size_t)D_DIM * D_DIM];    // qh,ql,kh,kl,vh,vl,oh,ol
__device__ bf16 g_Abt_h[(size_t)N_TOK * 640];
__device__ bf16 g_Abt_l[(size_t)N_TOK * 640];

// ======================= helpers ============================================
__device__ __forceinline__ uint32_t smem_u32(const void* p) {
    uint32_t a;
    asm("{ .reg .u64 t; cvta.to.shared.u64 t, %1; cvt.u32.u64 %0, t; }"
        : "=r"(a) : "l"(p));
    return a;
}
__device__ __forceinline__ void cp16(uint32_t dst, const void* src) {
    asm volatile("cp.async.cg.shared.global [%0], [%1], 16;" :: "r"(dst), "l"(src));
}
__device__ __forceinline__ void cp_commit() {
    asm volatile("cp.async.commit_group;" ::: "memory");
}
template <int NN_> __device__ __forceinline__ void cp_wait() {
    asm volatile("cp.async.wait_group %0;" :: "n"(NN_) : "memory");
}
__device__ __forceinline__ void ldm_x4(uint32_t& r0, uint32_t& r1, uint32_t& r2,
                                       uint32_t& r3, uint32_t addr) {
    asm volatile("ldmatrix.sync.aligned.m8n8.x4.shared.b16 {%0,%1,%2,%3}, [%4];"
                 : "=r"(r0), "=r"(r1), "=r"(r2), "=r"(r3) : "r"(addr));
}
__device__ __forceinline__ void ldm_x4t(uint32_t& r0, uint32_t& r1, uint32_t& r2,
                                        uint32_t& r3, uint32_t addr) {
    asm volatile("ldmatrix.sync.aligned.m8n8.x4.trans.shared.b16 {%0,%1,%2,%3}, [%4];"
                 : "=r"(r0), "=r"(r1), "=r"(r2), "=r"(r3) : "r"(addr));
}
__device__ __forceinline__ void mma_bf16(float* c, uint32_t a0, uint32_t a1,
                                         uint32_t a2, uint32_t a3,
                                         uint32_t b0, uint32_t b1) {
    asm volatile(
        "mma.sync.aligned.m16n8k16.row.col.f32.bf16.bf16.f32 "
        "{%0,%1,%2,%3}, {%4,%5,%6,%7}, {%8,%9}, {%0,%1,%2,%3};"
        : "+f"(c[0]), "+f"(c[1]), "+f"(c[2]), "+f"(c[3])
        : "r"(a0), "r"(a1), "r"(a2), "r"(a3), "r"(b0), "r"(b1));
}

// ======================= split fp32 -> bf16 hi/lo ===========================
__global__ __launch_bounds__(256)
void split_bf16(const float* __restrict__ s, bf16* __restrict__ hi,
                bf16* __restrict__ lo, int n4)
{
    int i = blockIdx.x * 256 + threadIdx.x;
    if (i >= n4) return;
    float4 v = ((const float4*)s)[i];
    bf16 h0 = __float2bfloat16(v.x);
    bf16 h1 = __float2bfloat16(v.y);
    bf16 h2 = __float2bfloat16(v.z);
    bf16 h3 = __float2bfloat16(v.w);
    bf16 l0 = __float2bfloat16(v.x - __bfloat162float(h0));
    bf16 l1 = __float2bfloat16(v.y - __bfloat162float(h1));
    bf16 l2 = __float2bfloat16(v.z - __bfloat162float(h2));
    bf16 l3 = __float2bfloat16(v.w - __bfloat162float(h3));
    __nv_bfloat162* hp = (__nv_bfloat162*)hi;
    __nv_bfloat162* lp = (__nv_bfloat162*)lo;
    hp[2 * i]     = __halves2bfloat162(h0, h1);
    hp[2 * i + 1] = __halves2bfloat162(h2, h3);
    lp[2 * i]     = __halves2bfloat162(l0, l1);
    lp[2 * i + 1] = __halves2bfloat162(l2, l3);
}

// ======================= GEMM tile constants ================================
#define TCK    32
#define NCH    (D_DIM / TCK)      // 32
#define ROWB   80
#define TILEB  (128 * ROWB)       // 10240
#define STAGEB (4 * TILEB)        // 40960
#define NSTAGE 2

#define DECL_FRAG_IDX                                        \
    const int lane = tid & 31;                               \
    const int wid  = tid >> 5;                               \
    const int wm   = wid & 1;                                \
    const int wn   = wid >> 1;                               \
    const int a_row = lane & 15;                             \
    const int a_kg  = (lane >> 4) * 8;                       \
    const int b_row = (lane & 7) + ((lane >> 4) << 3);       \
    const int b_kg  = ((lane >> 3) & 1) * 8;

// generic dense hi/lo mainloop body (A,B row-major [*,1024])
#define GEMM_MAINLOOP(SBEXPR, NCHUNKS, LOADFN)                                 \
    load_chunk(0, 0); cp_commit();                                             \
    load_chunk(1, 1); cp_commit();                                             \
    for (int c = 0; c < (NCHUNKS); c++) {                                      \
        cp_wait<NSTAGE - 1>();                                                 \
        __syncthreads();                                                       \
        const uint32_t sb = (SBEXPR);                                          \
        _Pragma("unroll")                                                      \
        for (int s = 0; s < 2; s++) {                                          \
            const int kc = s * 16;                                             \
            uint32_t ah[4][4], al[4][4], bh[2][4], bl[2][4];                   \
            _Pragma("unroll")                                                  \
            for (int mi = 0; mi < 4; mi++) {                                   \
                uint32_t ra = (wm * 64 + mi * 16 + a_row) * ROWB + (kc + a_kg) * 2; \
                ldm_x4(ah[mi][0], ah[mi][1], ah[mi][2], ah[mi][3], sb + ra);   \
                ldm_x4(al[mi][0], al[mi][1], al[mi][2], al[mi][3], sb + TILEB + ra); \
            }                                                                  \
            _Pragma("unroll")                                                  \
            for (int g = 0; g < 2; g++) {                                      \
                uint32_t rb = (wn * 32 + g * 16 + b_row) * ROWB + (kc + b_kg) * 2; \
                ldm_x4(bh[g][0], bh[g][1], bh[g][2], bh[g][3], sb + 2 * TILEB + rb); \
                ldm_x4(bl[g][0], bl[g][1], bl[g][2], bl[g][3], sb + 3 * TILEB + rb); \
            }                                                                  \
            _Pragma("unroll")                                                  \
            for (int mi = 0; mi < 4; mi++)                                     \
                _Pragma("unroll")                                              \
                for (int ni = 0; ni < 4; ni++) {                               \
                    uint32_t b0h = bh[ni >> 1][(ni & 1) * 2], b1h = bh[ni >> 1][(ni & 1) * 2 + 1]; \
                    uint32_t b0l = bl[ni >> 1][(ni & 1) * 2], b1l = bl[ni >> 1][(ni & 1) * 2 + 1]; \
                    mma_bf16(acc[mi][ni], ah[mi][0], ah[mi][1], ah[mi][2], ah[mi][3], b0h, b1h); \
                    mma_bf16(acc[mi][ni], ah[mi][0], ah[mi][1], ah[mi][2], ah[mi][3], b0l, b1l); \
                    mma_bf16(acc[mi][ni], al[mi][0], al[mi][1], al[mi][2], al[mi][3], b0h, b1h); \
                }                                                              \
        }                                                                      \
        __syncthreads();                                                       \
        if (c + NSTAGE < (NCHUNKS)) LOADFN(c + NSTAGE, c % NSTAGE);            \
        cp_commit();                                                           \
    }

#define ZERO_ACC                                             \
    float acc[4][4][4];                                      \
    _Pragma("unroll")                                        \
    for (int mi = 0; mi < 4; mi++)                           \
        _Pragma("unroll")                                    \
        for (int ni = 0; ni < 4; ni++)                       \
            _Pragma("unroll")                                \
            for (int q = 0; q < 4; q++) acc[mi][ni][q] = 0.f;

// ======================= fused QKV projection ===============================
// grid (8, 64, 3): z selects weight/output set. Writes bf16 hi/lo.
__global__ __launch_bounds__(256, 2)
void mma_gemm_qkv(const bf16* __restrict__ Ahi, const bf16* __restrict__ Alo,
                  const bf16* __restrict__ Wbase,
                  bf16* __restrict__ Phz, bf16* __restrict__ Plz)
{
    extern __shared__ __align__(128) char smem[];
    const uint32_t sbase = smem_u32(smem);
    const int tid = threadIdx.x;
    DECL_FRAG_IDX
    const int i0 = blockIdx.y * 128;
    const int j0 = blockIdx.x * 128;
    const int z  = blockIdx.z;
    const size_t WSZ = (size_t)D_DIM * D_DIM;
    const size_t ND  = (size_t)N_TOK * D_DIM;
    const float scale = (z == 0) ? 0.06f : 1.0f;

    const bf16* srcs[4] = {Ahi + (size_t)i0 * D_DIM, Alo + (size_t)i0 * D_DIM,
                           Wbase + 2 * z * WSZ + (size_t)j0 * D_DIM,
                           Wbase + (2 * z + 1) * WSZ + (size_t)j0 * D_DIM};
    bf16* Chi = Phz + z * ND;
    bf16* Clo = Plz + z * ND;

    auto load_chunk = [&](int c, int st) {
        const uint32_t sb = sbase + st * STAGEB;
        const int k0 = c * TCK;
#pragma unroll
        for (int t = 0; t < 4; t++) {
            const bf16* base = srcs[t] + k0;
            uint32_t dstb = sb + t * TILEB;
#pragma unroll
            for (int h = 0; h < 2; h++) {
                int idx = tid + h * 256;
                int r = idx >> 2, ck = idx & 3;
                cp16(dstb + r * ROWB + ck * 16, base + (size_t)r * D_DIM + ck * 8);
            }
        }
    };

    ZERO_ACC
    GEMM_MAINLOOP(sbase + (c % NSTAGE) * STAGEB, NCH, load_chunk)

    const int rbase = i0 + wm * 64;
    const int cbase = j0 + wn * 32;
#pragma unroll
    for (int mi = 0; mi < 4; mi++) {
        int r0 = rbase + mi * 16 + (lane >> 2);
#pragma unroll
        for (int ni = 0; ni < 4; ni++) {
            int cc = cbase + ni * 8 + (lane & 3) * 2;
#pragma unroll
            for (int hrow = 0; hrow < 2; hrow++) {
                float v0 = acc[mi][ni][hrow * 2 + 0] * scale;
                float v1 = acc[mi][ni][hrow * 2 + 1] * scale;
                bf16 h0 = __float2bfloat16(v0);
                bf16 h1 = __float2bfloat16(v1);
                bf16 l0 = __float2bfloat16(v0 - __bfloat162float(h0));
                bf16 l1 = __float2bfloat16(v1 - __bfloat162float(h1));
                size_t off = (size_t)(r0 + hrow * 8) * D_DIM + cc;
                *(__nv_bfloat162*)(Chi + off) = __halves2bfloat162(h0, h1);
                *(__nv_bfloat162*)(Clo + off) = __halves2bfloat162(l0, l1);
            }
        }
    }
}

// ======================= dense GEMM, fp32 output (final) ====================
__global__ __launch_bounds__(256, 2)
void mma_gemm_f32out(const bf16* __restrict__ Ahi, const bf16* __restrict__ Alo,
                     const bf16* __restrict__ Bhi, const bf16* __restrict__ Blo,
                     float* __restrict__ C)
{
    extern __shared__ __align__(128) char smem[];
    const uint32_t sbase = smem_u32(smem);
    const int tid = threadIdx.x;
    DECL_FRAG_IDX
    const int i0 = blockIdx.y * 128;
    const int j0 = blockIdx.x * 128;

    const bf16* srcs[4] = {Ahi + (size_t)i0 * D_DIM, Alo + (size_t)i0 * D_DIM,
                           Bhi + (size_t)j0 * D_DIM, Blo + (size_t)j0 * D_DIM};

    auto load_chunk = [&](int c, int st) {
        const uint32_t sb = sbase + st * STAGEB;
        const int k0 = c * TCK;
#pragma unroll
        for (int t = 0; t < 4; t++) {
            const bf16* base = srcs[t] + k0;
            uint32_t dstb = sb + t * TILEB;
#pragma unroll
            for (int h = 0; h < 2; h++) {
                int idx = tid + h * 256;
                int r = idx >> 2, ck = idx & 3;
                cp16(dstb + r * ROWB + ck * 16, base + (size_t)r * D_DIM + ck * 8);
            }
        }
    };

    ZERO_ACC
    GEMM_MAINLOOP(sbase + (c % NSTAGE) * STAGEB, NCH, load_chunk)

    const int rbase = i0 + wm * 64;
    const int cbase = j0 + wn * 32;
#pragma unroll
    for (int mi = 0; mi < 4; mi++) {
        int r0 = rbase + mi * 16 + (lane >> 2);
#pragma unroll
        for (int ni = 0; ni < 4; ni++) {
            int cc = cbase + ni * 8 + (lane & 3) * 2;
            *(float2*)(C + (size_t)r0 * D_DIM + cc) =
                make_float2(acc[mi][ni][0], acc[mi][ni][1]);
            *(float2*)(C + (size_t)(r0 + 8) * D_DIM + cc) =
                make_float2(acc[mi][ni][2], acc[mi][ni][3]);
        }
    }
}

// ======================= banded logits via mma ==============================
__global__ __launch_bounds__(256, 2)
void banded_logits_mma(const bf16* __restrict__ Qh, const bf16* __restrict__ Ql,
                       const bf16* __restrict__ Kh, const bf16* __restrict__ Kl,
                       float* __restrict__ Aband)
{
    extern __shared__ __align__(128) char smem[];
    const uint32_t sbase = smem_u32(smem);
    const int tid = threadIdx.x;
    DECL_FRAG_IDX
    const int i0 = blockIdx.y * 128;
    const int j0 = i0 + ((int)blockIdx.x - 2) * 128;

    auto load_chunk = [&](int c, int st) {
        const uint32_t sb = sbase + st * STAGEB;
        const int k0 = c * TCK;
#pragma unroll
        for (int t = 0; t < 2; t++) {
            const bf16* base = (t ? Ql : Qh) + k0;
            uint32_t dstb = sb + t * TILEB;
#pragma unroll
            for (int h = 0; h < 2; h++) {
                int idx = tid + h * 256;
                int r = idx >> 2, ck = idx & 3;
                cp16(dstb + r * ROWB + ck * 16, base + (size_t)(i0 + r) * D_DIM + ck * 8);
            }
        }
#pragma unroll
        for (int t = 0; t < 2; t++) {
            const bf16* base = (t ? Kl : Kh) + k0;
            uint32_t dstb = sb + (2 + t) * TILEB;
#pragma unroll
            for (int h = 0; h < 2; h++) {
                int idx = tid + h * 256;
                int r = idx >> 2, ck = idx & 3;
                int jr = j0 + r;
                jr = jr < 0 ? 0 : (jr >= N_TOK ? N_TOK - 1 : jr);
                cp16(dstb + r * ROWB + ck * 16, base + (size_t)jr * D_DIM + ck * 8);
            }
        }
    };

    ZERO_ACC
    GEMM_MAINLOOP(sbase + (c % NSTAGE) * STAGEB, NCH, load_chunk)

    const int rbase = i0 + wm * 64;
    const int cbase = j0 + wn * 32;
#pragma unroll
    for (int mi = 0; mi < 4; mi++) {
#pragma unroll
        for (int hrow = 0; hrow < 2; hrow++) {
            int i = rbase + mi * 16 + (lane >> 2) + hrow * 8;
#pragma unroll
            for (int ni = 0; ni < 4; ni++) {
#pragma unroll
                for (int q = 0; q < 2; q++) {
                    int j = cbase + ni * 8 + (lane & 3) * 2 + q;
                    int t = j - i + 249;
                    if ((unsigned)j < (unsigned)N_TOK && (unsigned)t < (unsigned)BVAL)
                        Aband[(size_t)i * BW + t] = acc[mi][ni][hrow * 2 + q];
                }
            }
        }
    }
}

// ---------------- per-row band softmax (in place) ---------------------------
__global__ __launch_bounds__(128)
void band_softmax(float* __restrict__ Aband)
{
    const int i = blockIdx.x;
    const int tlo = max(0, 249 - i);
    const int thi = min(BVAL - 1, N_TOK - 1 - i + 249);
    const int tid = threadIdx.x;
    float* row = Aband + (size_t)i * BW;

    __shared__ float red[128];

    float mx = -INFINITY;
    for (int t = tlo + tid; t <= thi; t += 128) mx = fmaxf(mx, row[t]);
    red[tid] = mx; __syncthreads();
    for (int s = 64; s > 0; s >>= 1) {
        if (tid < s) red[tid] = fmaxf(red[tid], red[tid + s]);
        __syncthreads();
    }
    mx = red[0]; __syncthreads();

    float sum = 0.f;
    for (int t = tlo + tid; t <= thi; t += 128) {
        float e = __expf(row[t] - mx);
        row[t] = e;
        sum += e;
    }
    red[tid] = sum; __syncthreads();
    for (int s = 64; s > 0; s >>= 1) {
        if (tid < s) red[tid] += red[tid + s];
        __syncthreads();
    }
    float inv = 1.f / red[0]; __syncthreads();

    for (int t = tlo + tid; t <= thi; t += 128) row[t] *= inv;
}

// -------- transpose band weights into per-block K-aligned bf16 hi/lo --------
__global__ __launch_bounds__(256)
void band_transpose(const float* __restrict__ Aband,
                    bf16* __restrict__ Abt_h, bf16* __restrict__ Abt_l)
{
    const int jb = blockIdx.z;
    const int j0l = blockIdx.y * 64;
    const int ii0 = blockIdx.x * 64;
    const int j0 = jb * 128 + j0l;
    const int ibase = jb * 128 - 256 + ii0;
    const int tid = threadIdx.x;

    __shared__ float ts[64][65];

    for (int e = tid; e < 64 * 64; e += 256) {
        int r = e >> 6, jc = e & 63;
        int i = ibase + r, j = j0 + jc;
        int t = j - i + 249;
        float v = 0.f;
        if ((unsigned)i < (unsigned)N_TOK && (unsigned)t < (unsigned)BVAL)
            v = Aband[(size_t)i * BW + t];
        ts[r][jc] = v;
    }
    __syncthreads();

    for (int e = tid; e < 64 * 64; e += 256) {
        int jc = e >> 6, r = e & 63;
        float v = ts[r][jc];
        bf16 h = __float2bfloat16(v);
        bf16 l = __float2bfloat16(v - __bfloat162float(h));
        size_t off = ((size_t)jb * 128 + j0l + jc) * 640 + ii0 + r;
        Abt_h[off] = h;
        Abt_l[off] = l;
    }
}

// ======================= banded A^T@V via mma ===============================
#define AVK    640
#define NCH2   (AVK / TCK)        // 20
#define ROWVB  272
#define VTILEB (32 * ROWVB)       // 8704
#define AVSTAGE (2 * TILEB + 2 * VTILEB)  // 37888

__global__ __launch_bounds__(256, 2)
void banded_av_mma(const bf16* __restrict__ Abt_h, const bf16* __restrict__ Abt_l,
                   const bf16* __restrict__ Vh, const bf16* __restrict__ Vl,
                   bf16* __restrict__ Yh, bf16* __restrict__ Yl)
{
    extern __shared__ __align__(128) char smem[];
    const uint32_t sbase = smem_u32(smem);
    const int tid = threadIdx.x;
    DECL_FRAG_IDX
    const int jb = blockIdx.y;
    const int d0 = blockIdx.x * 128;
    const int jbase = jb * 128 - 256;

    const bf16* Ab[2] = {Abt_h + (size_t)jb * 128 * 640, Abt_l + (size_t)jb * 128 * 640};
    const bf16* Vb[2] = {Vh, Vl};

    auto load_chunk = [&](int c, int st) {
        const uint32_t sb = sbase + st * AVSTAGE;
        const int k0 = c * TCK;
#pragma unroll
        for (int t = 0; t < 2; t++) {
            const bf16* base = Ab[t] + k0;
            uint32_t dstb = sb + t * TILEB;
#pragma unroll
            for (int h = 0; h < 2; h++) {
                int idx = tid + h * 256;
                int r = idx >> 2, ck = idx & 3;
                cp16(dstb + r * ROWB + ck * 16, base + (size_t)r * 640 + ck * 8);
            }
        }
#pragma unroll
        for (int t = 0; t < 2; t++) {
            const bf16* base = Vb[t] + d0;
            uint32_t dstb = sb + 2 * TILEB + t * VTILEB;
#pragma unroll
            for (int h = 0; h < 2; h++) {
                int idx = tid + h * 256;
                int r = idx >> 4, ck = idx & 15;
                int i = jbase + k0 + r;
                i = i < 0 ? 0 : (i >= N_TOK ? N_TOK - 1 : i);
                cp16(dstb + r * ROWVB + ck * 16, base + (size_t)i * D_DIM + ck * 8);
            }
        }
    };

    float acc[4][4][4];
#pragma unroll
    for (int mi = 0; mi < 4; mi++)
#pragma unroll
        for (int ni = 0; ni < 4; ni++)
#pragma unroll
            for (int q = 0; q < 4; q++) acc[mi][ni][q] = 0.f;

    load_chunk(0, 0); cp_commit();
    load_chunk(1, 1); cp_commit();

    for (int c = 0; c < NCH2; c++) {
        cp_wait<NSTAGE - 1>();
        __syncthreads();
        const uint32_t sb = sbase + (c % NSTAGE) * AVSTAGE;
#pragma unroll
        for (int s = 0; s < 2; s++) {
            const int kc = s * 16;
            uint32_t ah[4][4], al[4][4], bh[2][4], bl[2][4];
#pragma unroll
            for (int mi = 0; mi < 4; mi++) {
                uint32_t ra = (wm * 64 + mi * 16 + a_row) * ROWB + (kc + a_kg) * 2;
                ldm_x4(ah[mi][0], ah[mi][1], ah[mi][2], ah[mi][3], sb + ra);
                ldm_x4(al[mi][0], al[mi][1], al[mi][2], al[mi][3], sb + TILEB + ra);
            }
#pragma unroll
            for (int g = 0; g < 2; g++) {
                uint32_t rb = (uint32_t)(kc + (lane & 15)) * ROWVB
                            + (wn * 32 + g * 16 + (lane >> 4) * 8) * 2;
                ldm_x4t(bh[g][0], bh[g][1], bh[g][2], bh[g][3], sb + 2 * TILEB + rb);
                ldm_x4t(bl[g][0], bl[g][1], bl[g][2], bl[g][3], sb + 2 * TILEB + VTILEB + rb);
            }
#pragma unroll
            for (int mi = 0; mi < 4; mi++)
#pragma unroll
                for (int ni = 0; ni < 4; ni++) {
                    uint32_t b0h = bh[ni >> 1][(ni & 1) * 2], b1h = bh[ni >> 1][(ni & 1) * 2 + 1];
                    uint32_t b0l = bl[ni >> 1][(ni & 1) * 2], b1l = bl[ni >> 1][(ni & 1) * 2 + 1];
                    mma_bf16(acc[mi][ni], ah[mi][0], ah[mi][1], ah[mi][2], ah[mi][3], b0h, b1h);
                    mma_bf16(acc[mi][ni], ah[mi][0], ah[mi][1], ah[mi][2], ah[mi][3], b0l, b1l);
                    mma_bf16(acc[mi][ni], al[mi][0], al[mi][1], al[mi][2], al[mi][3], b0h, b1h);
                }
        }
        __syncthreads();
        if (c + NSTAGE < NCH2) load_chunk(c + NSTAGE, c % NSTAGE);
        cp_commit();
    }

    const int rbase = jb * 128 + wm * 64;
    const int cbase = d0 + wn * 32;
#pragma unroll
    for (int mi = 0; mi < 4; mi++) {
        int r0 = rbase + mi * 16 + (lane >> 2);
#pragma unroll
        for (int ni = 0; ni < 4; ni++) {
            int cc = cbase + ni * 8 + (lane & 3) * 2;
#pragma unroll
            for (int hrow = 0; hrow < 2; hrow++) {
                float v0 = acc[mi][ni][hrow * 2 + 0];
                float v1 = acc[mi][ni][hrow * 2 + 1];
                bf16 h0 = __float2bfloat16(v0);
                bf16 h1 = __float2bfloat16(v1);
                bf16 l0 = __float2bfloat16(v0 - __bfloat162float(h0));
                bf16 l1 = __float2bfloat16(v1 - __bfloat162float(h1));
                size_t off = (size_t)(r0 + hrow * 8) * D_DIM + cc;
                *(__nv_bfloat162*)(Yh + off) = __halves2bfloat162(h0, h1);
                *(__nv_bfloat162*)(Yl + off) = __halves2bfloat162(l0, l1);
            }
        }
    }
}

// ---------------- expand band weights to dense att output -------------------
__global__ __launch_bounds__(256)
void write_att(const float* __restrict__ Aband, float* __restrict__ att)
{
    const int i = blockIdx.y;
    const int j = (blockIdx.x * 256 + threadIdx.x) * 4;
    float4 o;
    float r[4];
#pragma unroll
    for (int q = 0; q < 4; q++) {
        int t = j + q - i + 249;
        r[q] = ((unsigned)t < (unsigned)BVAL) ? Aband[(size_t)i * BW + t] : 0.f;
    }
    o.x = r[0]; o.y = r[1]; o.z = r[2]; o.w = r[3];
    *(float4*)(att + (size_t)i * N_TOK + j) = o;
}

// ---------------------------------------------------------------------------
extern "C" void kernel_launch(void* const* d_in, const int* in_sizes, int n_in,
                              void* d_out, int out_size)
{
    const float* x  = (const float*)d_in[0];
    const float* Wq = (const float*)d_in[1];
    const float* Wk = (const float*)d_in[2];
    const float* Wv = (const float*)d_in[3];
    const float* Wo = (const float*)d_in[4];

    float *pA, *pYd;
    cudaGetSymbolAddress((void**)&pA, g_A);
    cudaGetSymbolAddress((void**)&pYd, g_Ydump);

    bf16 *xhi, *xlo, *ph, *pl, *yh, *yl, *wsp, *abth, *abtl;
    cudaGetSymbolAddress((void**)&xhi, g_xhi);
    cudaGetSymbolAddress((void**)&xlo, g_xlo);
    cudaGetSymbolAddress((void**)&ph, g_Ph);
    cudaGetSymbolAddress((void**)&pl, g_Pl);
    cudaGetSymbolAddress((void**)&yh, g_Yh);
    cudaGetSymbolAddress((void**)&yl, g_Yl);
    cudaGetSymbolAddress((void**)&wsp, g_w);
    cudaGetSymbolAddress((void**)&abth, g_Abt_h);
    cudaGetSymbolAddress((void**)&abtl, g_Abt_l);

    const size_t WSZ = (size_t)D_DIM * D_DIM;
    const size_t NDe = (size_t)N_TOK * D_DIM;
    bf16* wq_h = wsp + 0 * WSZ; bf16* wq_l = wsp + 1 * WSZ;
    bf16* wk_h = wsp + 2 * WSZ; bf16* wk_l = wsp + 3 * WSZ;
    bf16* wv_h = wsp + 4 * WSZ; bf16* wv_l = wsp + 5 * WSZ;
    bf16* wo_h = wsp + 6 * WSZ; bf16* wo_l = wsp + 7 * WSZ;

    bf16* qh = ph + 0 * NDe; bf16* ql = pl + 0 * NDe;
    bf16* kh = ph + 1 * NDe; bf16* kl = pl + 1 * NDe;
    bf16* vh = ph + 2 * NDe; bf16* vl = pl + 2 * NDe;

    const long ND = (long)N_TOK * D_DIM;
    const long NN = (long)N_TOK * N_TOK;

    float* out = (float*)d_out;
    float* yout = out;
    float* attout = nullptr;
    if ((long)out_size >= ND + NN) {
        yout = out;
        attout = out + ND;
    } else if ((long)out_size == NN) {
        yout = pYd;
        attout = out;
    }

    const int SMEM_GEMM = NSTAGE * STAGEB;      // 81920
    const int SMEM_AV   = NSTAGE * AVSTAGE;     // 75776
    cudaFuncSetAttribute(mma_gemm_qkv, cudaFuncAttributeMaxDynamicSharedMemorySize, SMEM_GEMM);
    cudaFuncSetAttribute(mma_gemm_f32out, cudaFuncAttributeMaxDynamicSharedMemorySize, SMEM_GEMM);
    cudaFuncSetAttribute(banded_logits_mma, cudaFuncAttributeMaxDynamicSharedMemorySize, SMEM_GEMM);
    cudaFuncSetAttribute(banded_av_mma, cudaFuncAttributeMaxDynamicSharedMemorySize, SMEM_AV);

    // splits
    split_bf16<<<(N_TOK * D_DIM / 4 + 255) / 256, 256>>>(x, xhi, xlo, N_TOK * D_DIM / 4);
    split_bf16<<<(D_DIM * D_DIM / 4 + 255) / 256, 256>>>(Wq, wq_h, wq_l, D_DIM * D_DIM / 4);
    split_bf16<<<(D_DIM * D_DIM / 4 + 255) / 256, 256>>>(Wk, wk_h, wk_l, D_DIM * D_DIM / 4);
    split_bf16<<<(D_DIM * D_DIM / 4 + 255) / 256, 256>>>(Wv, wv_h, wv_l, D_DIM * D_DIM / 4);
    split_bf16<<<(D_DIM * D_DIM / 4 + 255) / 256, 256>>>(Wo, wo_h, wo_l, D_DIM * D_DIM / 4);

    // fused QKV projection (z = 0,1,2)
    mma_gemm_qkv<<<dim3(D_DIM / 128, N_TOK / 128, 3), 256, SMEM_GEMM>>>(xhi, xlo, wsp, ph, pl);

    // banded attention
    banded_logits_mma<<<dim3(5, N_TOK / 128), 256, SMEM_GEMM>>>(qh, ql, kh, kl, pA);
    band_softmax<<<N_TOK, 128>>>(pA);
    band_transpose<<<dim3(10, 2, N_TOK / 128), 256>>>(pA, abth, abtl);
    banded_av_mma<<<dim3(D_DIM / 128, N_TOK / 128), 256, SMEM_AV>>>(abth, abtl, vh, vl, yh, yl);

    // output projection
    mma_gemm_f32out<<<dim3(D_DIM / 128, N_TOK / 128), 256, SMEM_GEMM>>>(yh, yl, wo_h, wo_l, yout);

    if (attout)
        write_att<<<dim3(N_TOK / 1024, N_TOK), 256>>>(pA, attout);
}

// round 10
// speedup vs baseline: 2.6753x; 1.0301x over previous
#include <cuda_runtime.h>
#include <cuda_bf16.h>
#include <math.h>
#include <stdint.h>

#define N_TOK 8192
#define D_DIM 1024
#define BW    512
#define BVAL  499

typedef __nv_bfloat16 bf16;

// ---------------- scratch (static device arrays, no allocation) -------------
__device__ float g_A[(size_t)N_TOK * BW];        // logits half 0 -> weights
__device__ float g_A2[(size_t)N_TOK * BW];       // logits half 1
__device__ float g_Ydump[(size_t)N_TOK * D_DIM];

__device__ bf16 g_xhi[(size_t)N_TOK * D_DIM];
__device__ bf16 g_xlo[(size_t)N_TOK * D_DIM];
__device__ bf16 g_Ph[3][(size_t)N_TOK * D_DIM];   // Q,K,V hi
__device__ bf16 g_Pl[3][(size_t)N_TOK * D_DIM];   // Q,K,V lo
__device__ bf16 g_Yh[(size_t)N_TOK * D_DIM];
__device__ bf16 g_Yl[(size_t)N_TOK * D_DIM];
__device__ bf16 g_w[8][(size_t)D_DIM * D_DIM];    // qh,ql,kh,kl,vh,vl,oh,ol
__device__ bf16 g_Abt_h[(size_t)N_TOK * 640];
__device__ bf16 g_Abt_l[(size_t)N_TOK * 640];

// ======================= helpers ============================================
__device__ __forceinline__ uint32_t smem_u32(const void* p) {
    uint32_t a;
    asm("{ .reg .u64 t; cvta.to.shared.u64 t, %1; cvt.u32.u64 %0, t; }"
        : "=r"(a) : "l"(p));
    return a;
}
__device__ __forceinline__ void cp16(uint32_t dst, const void* src) {
    asm volatile("cp.async.cg.shared.global [%0], [%1], 16;" :: "r"(dst), "l"(src));
}
__device__ __forceinline__ void cp_commit() {
    asm volatile("cp.async.commit_group;" ::: "memory");
}
template <int NN_> __device__ __forceinline__ void cp_wait() {
    asm volatile("cp.async.wait_group %0;" :: "n"(NN_) : "memory");
}
__device__ __forceinline__ void ldm_x4(uint32_t& r0, uint32_t& r1, uint32_t& r2,
                                       uint32_t& r3, uint32_t addr) {
    asm volatile("ldmatrix.sync.aligned.m8n8.x4.shared.b16 {%0,%1,%2,%3}, [%4];"
                 : "=r"(r0), "=r"(r1), "=r"(r2), "=r"(r3) : "r"(addr));
}
__device__ __forceinline__ void ldm_x4t(uint32_t& r0, uint32_t& r1, uint32_t& r2,
                                        uint32_t& r3, uint32_t addr) {
    asm volatile("ldmatrix.sync.aligned.m8n8.x4.trans.shared.b16 {%0,%1,%2,%3}, [%4];"
                 : "=r"(r0), "=r"(r1), "=r"(r2), "=r"(r3) : "r"(addr));
}
__device__ __forceinline__ void mma_bf16(float* c, uint32_t a0, uint32_t a1,
                                         uint32_t a2, uint32_t a3,
                                         uint32_t b0, uint32_t b1) {
    asm volatile(
        "mma.sync.aligned.m16n8k16.row.col.f32.bf16.bf16.f32 "
        "{%0,%1,%2,%3}, {%4,%5,%6,%7}, {%8,%9}, {%0,%1,%2,%3};"
        : "+f"(c[0]), "+f"(c[1]), "+f"(c[2]), "+f"(c[3])
        : "r"(a0), "r"(a1), "r"(a2), "r"(a3), "r"(b0), "r"(b1));
}

// ======================= split fp32 -> bf16 hi/lo ===========================
__global__ __launch_bounds__(256)
void split_bf16(const float* __restrict__ s, bf16* __restrict__ hi,
                bf16* __restrict__ lo, int n4)
{
    int i = blockIdx.x * 256 + threadIdx.x;
    if (i >= n4) return;
    float4 v = ((const float4*)s)[i];
    bf16 h0 = __float2bfloat16(v.x);
    bf16 h1 = __float2bfloat16(v.y);
    bf16 h2 = __float2bfloat16(v.z);
    bf16 h3 = __float2bfloat16(v.w);
    bf16 l0 = __float2bfloat16(v.x - __bfloat162float(h0));
    bf16 l1 = __float2bfloat16(v.y - __bfloat162float(h1));
    bf16 l2 = __float2bfloat16(v.z - __bfloat162float(h2));
    bf16 l3 = __float2bfloat16(v.w - __bfloat162float(h3));
    __nv_bfloat162* hp = (__nv_bfloat162*)hi;
    __nv_bfloat162* lp = (__nv_bfloat162*)lo;
    hp[2 * i]     = __halves2bfloat162(h0, h1);
    hp[2 * i + 1] = __halves2bfloat162(h2, h3);
    lp[2 * i]     = __halves2bfloat162(l0, l1);
    lp[2 * i + 1] = __halves2bfloat162(l2, l3);
}

// ======================= GEMM tile constants ================================
#define TCK    32
#define NCH    (D_DIM / TCK)      // 32
#define ROWB   80
#define TILEB  (128 * ROWB)       // 10240
#define STAGEB (4 * TILEB)        // 40960
#define NSTAGE 2

#define DECL_FRAG_IDX                                        \
    const int lane = tid & 31;                               \
    const int wid  = tid >> 5;                               \
    const int wm   = wid & 1;                                \
    const int wn   = wid >> 1;                               \
    const int a_row = lane & 15;                             \
    const int a_kg  = (lane >> 4) * 8;                       \
    const int b_row = (lane & 7) + ((lane >> 4) << 3);       \
    const int b_kg  = ((lane >> 3) & 1) * 8;

#define GEMM_MAINLOOP(SBEXPR, NCHUNKS, LOADFN)                                 \
    load_chunk(0, 0); cp_commit();                                             \
    load_chunk(1, 1); cp_commit();                                             \
    for (int c = 0; c < (NCHUNKS); c++) {                                      \
        cp_wait<NSTAGE - 1>();                                                 \
        __syncthreads();                                                       \
        const uint32_t sb = (SBEXPR);                                          \
        _Pragma("unroll")                                                      \
        for (int s = 0; s < 2; s++) {                                          \
            const int kc = s * 16;                                             \
            uint32_t ah[4][4], al[4][4], bh[2][4], bl[2][4];                   \
            _Pragma("unroll")                                                  \
            for (int mi = 0; mi < 4; mi++) {                                   \
                uint32_t ra = (wm * 64 + mi * 16 + a_row) * ROWB + (kc + a_kg) * 2; \
                ldm_x4(ah[mi][0], ah[mi][1], ah[mi][2], ah[mi][3], sb + ra);   \
                ldm_x4(al[mi][0], al[mi][1], al[mi][2], al[mi][3], sb + TILEB + ra); \
            }                                                                  \
            _Pragma("unroll")                                                  \
            for (int g = 0; g < 2; g++) {                                      \
                uint32_t rb = (wn * 32 + g * 16 + b_row) * ROWB + (kc + b_kg) * 2; \
                ldm_x4(bh[g][0], bh[g][1], bh[g][2], bh[g][3], sb + 2 * TILEB + rb); \
                ldm_x4(bl[g][0], bl[g][1], bl[g][2], bl[g][3], sb + 3 * TILEB + rb); \
            }                                                                  \
            _Pragma("unroll")                                                  \
            for (int mi = 0; mi < 4; mi++)                                     \
                _Pragma("unroll")                                              \
                for (int ni = 0; ni < 4; ni++) {                               \
                    uint32_t b0h = bh[ni >> 1][(ni & 1) * 2], b1h = bh[ni >> 1][(ni & 1) * 2 + 1]; \
                    uint32_t b0l = bl[ni >> 1][(ni & 1) * 2], b1l = bl[ni >> 1][(ni & 1) * 2 + 1]; \
                    mma_bf16(acc[mi][ni], ah[mi][0], ah[mi][1], ah[mi][2], ah[mi][3], b0h, b1h); \
                    mma_bf16(acc[mi][ni], ah[mi][0], ah[mi][1], ah[mi][2], ah[mi][3], b0l, b1l); \
                    mma_bf16(acc[mi][ni], al[mi][0], al[mi][1], al[mi][2], al[mi][3], b0h, b1h); \
                }                                                              \
        }                                                                      \
        __syncthreads();                                                       \
        if (c + NSTAGE < (NCHUNKS)) LOADFN(c + NSTAGE, c % NSTAGE);            \
        cp_commit();                                                           \
    }

#define ZERO_ACC                                             \
    float acc[4][4][4];                                      \
    _Pragma("unroll")                                        \
    for (int mi = 0; mi < 4; mi++)                           \
        _Pragma("unroll")                                    \
        for (int ni = 0; ni < 4; ni++)                       \
            _Pragma("unroll")                                \
            for (int q = 0; q < 4; q++) acc[mi][ni][q] = 0.f;

// ======================= fused QKV projection ===============================
__global__ __launch_bounds__(256, 2)
void mma_gemm_qkv(const bf16* __restrict__ Ahi, const bf16* __restrict__ Alo,
                  const bf16* __restrict__ Wbase,
                  bf16* __restrict__ Phz, bf16* __restrict__ Plz)
{
    extern __shared__ __align__(128) char smem[];
    const uint32_t sbase = smem_u32(smem);
    const int tid = threadIdx.x;
    DECL_FRAG_IDX
    const int i0 = blockIdx.y * 128;
    const int j0 = blockIdx.x * 128;
    const int z  = blockIdx.z;
    const size_t WSZ = (size_t)D_DIM * D_DIM;
    const size_t ND  = (size_t)N_TOK * D_DIM;
    const float scale = (z == 0) ? 0.06f : 1.0f;

    const bf16* srcs[4] = {Ahi + (size_t)i0 * D_DIM, Alo + (size_t)i0 * D_DIM,
                           Wbase + 2 * z * WSZ + (size_t)j0 * D_DIM,
                           Wbase + (2 * z + 1) * WSZ + (size_t)j0 * D_DIM};
    bf16* Chi = Phz + z * ND;
    bf16* Clo = Plz + z * ND;

    auto load_chunk = [&](int c, int st) {
        const uint32_t sb = sbase + st * STAGEB;
        const int k0 = c * TCK;
#pragma unroll
        for (int t = 0; t < 4; t++) {
            const bf16* base = srcs[t] + k0;
            uint32_t dstb = sb + t * TILEB;
#pragma unroll
            for (int h = 0; h < 2; h++) {
                int idx = tid + h * 256;
                int r = idx >> 2, ck = idx & 3;
                cp16(dstb + r * ROWB + ck * 16, base + (size_t)r * D_DIM + ck * 8);
            }
        }
    };

    ZERO_ACC
    GEMM_MAINLOOP(sbase + (c % NSTAGE) * STAGEB, NCH, load_chunk)

    const int rbase = i0 + wm * 64;
    const int cbase = j0 + wn * 32;
#pragma unroll
    for (int mi = 0; mi < 4; mi++) {
        int r0 = rbase + mi * 16 + (lane >> 2);
#pragma unroll
        for (int ni = 0; ni < 4; ni++) {
            int cc = cbase + ni * 8 + (lane & 3) * 2;
#pragma unroll
            for (int hrow = 0; hrow < 2; hrow++) {
                float v0 = acc[mi][ni][hrow * 2 + 0] * scale;
                float v1 = acc[mi][ni][hrow * 2 + 1] * scale;
                bf16 h0 = __float2bfloat16(v0);
                bf16 h1 = __float2bfloat16(v1);
                bf16 l0 = __float2bfloat16(v0 - __bfloat162float(h0));
                bf16 l1 = __float2bfloat16(v1 - __bfloat162float(h1));
                size_t off = (size_t)(r0 + hrow * 8) * D_DIM + cc;
                *(__nv_bfloat162*)(Chi + off) = __halves2bfloat162(h0, h1);
                *(__nv_bfloat162*)(Clo + off) = __halves2bfloat162(l0, l1);
            }
        }
    }
}

// ======================= dense GEMM, fp32 output (final) ====================
__global__ __launch_bounds__(256, 2)
void mma_gemm_f32out(const bf16* __restrict__ Ahi, const bf16* __restrict__ Alo,
                     const bf16* __restrict__ Bhi, const bf16* __restrict__ Blo,
                     float* __restrict__ C)
{
    extern __shared__ __align__(128) char smem[];
    const uint32_t sbase = smem_u32(smem);
    const int tid = threadIdx.x;
    DECL_FRAG_IDX
    const int i0 = blockIdx.y * 128;
    const int j0 = blockIdx.x * 128;

    const bf16* srcs[4] = {Ahi + (size_t)i0 * D_DIM, Alo + (size_t)i0 * D_DIM,
                           Bhi + (size_t)j0 * D_DIM, Blo + (size_t)j0 * D_DIM};

    auto load_chunk = [&](int c, int st) {
        const uint32_t sb = sbase + st * STAGEB;
        const int k0 = c * TCK;
#pragma unroll
        for (int t = 0; t < 4; t++) {
            const bf16* base = srcs[t] + k0;
            uint32_t dstb = sb + t * TILEB;
#pragma unroll
            for (int h = 0; h < 2; h++) {
                int idx = tid + h * 256;
                int r = idx >> 2, ck = idx & 3;
                cp16(dstb + r * ROWB + ck * 16, base + (size_t)r * D_DIM + ck * 8);
            }
        }
    };

    ZERO_ACC
    GEMM_MAINLOOP(sbase + (c % NSTAGE) * STAGEB, NCH, load_chunk)

    const int rbase = i0 + wm * 64;
    const int cbase = j0 + wn * 32;
#pragma unroll
    for (int mi = 0; mi < 4; mi++) {
        int r0 = rbase + mi * 16 + (lane >> 2);
#pragma unroll
        for (int ni = 0; ni < 4; ni++) {
            int cc = cbase + ni * 8 + (lane & 3) * 2;
            *(float2*)(C + (size_t)r0 * D_DIM + cc) =
                make_float2(acc[mi][ni][0], acc[mi][ni][1]);
            *(float2*)(C + (size_t)(r0 + 8) * D_DIM + cc) =
                make_float2(acc[mi][ni][2], acc[mi][ni][3]);
        }
    }
}

// ======================= banded logits via mma (split-K) ====================
// grid (5, 64, 2): i0 = by*128, j0 = i0 + (bx-2)*128, z = K half.
__global__ __launch_bounds__(256, 2)
void banded_logits_mma(const bf16* __restrict__ Qh, const bf16* __restrict__ Ql,
                       const bf16* __restrict__ Kh, const bf16* __restrict__ Kl,
                       float* __restrict__ A0, float* __restrict__ A1)
{
    extern __shared__ __align__(128) char smem[];
    const uint32_t sbase = smem_u32(smem);
    const int tid = threadIdx.x;
    DECL_FRAG_IDX
    const int i0 = blockIdx.y * 128;
    const int j0 = i0 + ((int)blockIdx.x - 2) * 128;
    const int kbase = blockIdx.z * (D_DIM / 2);
    float* Aout = blockIdx.z ? A1 : A0;

    auto load_chunk = [&](int c, int st) {
        const uint32_t sb = sbase + st * STAGEB;
        const int k0 = kbase + c * TCK;
#pragma unroll
        for (int t = 0; t < 2; t++) {
            const bf16* base = (t ? Ql : Qh) + k0;
            uint32_t dstb = sb + t * TILEB;
#pragma unroll
            for (int h = 0; h < 2; h++) {
                int idx = tid + h * 256;
                int r = idx >> 2, ck = idx & 3;
                cp16(dstb + r * ROWB + ck * 16, base + (size_t)(i0 + r) * D_DIM + ck * 8);
            }
        }
#pragma unroll
        for (int t = 0; t < 2; t++) {
            const bf16* base = (t ? Kl : Kh) + k0;
            uint32_t dstb = sb + (2 + t) * TILEB;
#pragma unroll
            for (int h = 0; h < 2; h++) {
                int idx = tid + h * 256;
                int r = idx >> 2, ck = idx & 3;
                int jr = j0 + r;
                jr = jr < 0 ? 0 : (jr >= N_TOK ? N_TOK - 1 : jr);
                cp16(dstb + r * ROWB + ck * 16, base + (size_t)jr * D_DIM + ck * 8);
            }
        }
    };

    ZERO_ACC
    GEMM_MAINLOOP(sbase + (c % NSTAGE) * STAGEB, NCH / 2, load_chunk)

    const int rbase = i0 + wm * 64;
    const int cbase = j0 + wn * 32;
#pragma unroll
    for (int mi = 0; mi < 4; mi++) {
#pragma unroll
        for (int hrow = 0; hrow < 2; hrow++) {
            int i = rbase + mi * 16 + (lane >> 2) + hrow * 8;
#pragma unroll
            for (int ni = 0; ni < 4; ni++) {
#pragma unroll
                for (int q = 0; q < 2; q++) {
                    int j = cbase + ni * 8 + (lane & 3) * 2 + q;
                    int t = j - i + 249;
                    if ((unsigned)j < (unsigned)N_TOK && (unsigned)t < (unsigned)BVAL)
                        Aout[(size_t)i * BW + t] = acc[mi][ni][hrow * 2 + q];
                }
            }
        }
    }
}

// ---- fused: sum K-halves, band softmax, write weights + dense att row ------
__global__ __launch_bounds__(256)
void band_softmax_att(float* __restrict__ A0, const float* __restrict__ A1,
                      float* __restrict__ att)
{
    const int i = blockIdx.x;
    const int tlo = max(0, 249 - i);
    const int thi = min(BVAL - 1, N_TOK - 1 - i + 249);
    const int tid = threadIdx.x;
    float* row        = A0 + (size_t)i * BW;
    const float* row2 = A1 + (size_t)i * BW;

    __shared__ float red[256];
    __shared__ float sband[512];

    float mx = -INFINITY;
    for (int t = tlo + tid; t <= thi; t += 256) mx = fmaxf(mx, row[t] + row2[t]);
    red[tid] = mx; __syncthreads();
    for (int s = 128; s > 0; s >>= 1) {
        if (tid < s) red[tid] = fmaxf(red[tid], red[tid + s]);
        __syncthreads();
    }
    mx = red[0]; __syncthreads();

    float sum = 0.f;
    for (int t = tlo + tid; t <= thi; t += 256) {
        float e = __expf(row[t] + row2[t] - mx);
        sband[t] = e;
        sum += e;
    }
    red[tid] = sum; __syncthreads();
    for (int s = 128; s > 0; s >>= 1) {
        if (tid < s) red[tid] += red[tid + s];
        __syncthreads();
    }
    float inv = 1.f / red[0]; __syncthreads();

    for (int t = tlo + tid; t <= thi; t += 256) {
        float w = sband[t] * inv;
        sband[t] = w;
        row[t] = w;                 // normalized weights for transpose/AV
    }
    __syncthreads();

    if (att) {
        float* arow = att + (size_t)i * N_TOK;
        for (int j4 = tid * 4; j4 < N_TOK; j4 += 256 * 4) {
            float4 o;
            float r[4];
#pragma unroll
            for (int q = 0; q < 4; q++) {
                int t = j4 + q - i + 249;
                r[q] = ((unsigned)t < (unsigned)BVAL) ? sband[t] : 0.f;
            }
            o.x = r[0]; o.y = r[1]; o.z = r[2]; o.w = r[3];
            *(float4*)(arow + j4) = o;
        }
    }
}

// -------- transpose band weights into per-block K-aligned bf16 hi/lo --------
__global__ __launch_bounds__(256)
void band_transpose(const float* __restrict__ Aband,
                    bf16* __restrict__ Abt_h, bf16* __restrict__ Abt_l)
{
    const int jb = blockIdx.z;
    const int j0l = blockIdx.y * 64;
    const int ii0 = blockIdx.x * 64;
    const int j0 = jb * 128 + j0l;
    const int ibase = jb * 128 - 256 + ii0;
    const int tid = threadIdx.x;

    __shared__ float ts[64][65];

    for (int e = tid; e < 64 * 64; e += 256) {
        int r = e >> 6, jc = e & 63;
        int i = ibase + r, j = j0 + jc;
        int t = j - i + 249;
        float v = 0.f;
        if ((unsigned)i < (unsigned)N_TOK && (unsigned)t < (unsigned)BVAL)
            v = Aband[(size_t)i * BW + t];
        ts[r][jc] = v;
    }
    __syncthreads();

    for (int e = tid; e < 64 * 64; e += 256) {
        int jc = e >> 6, r = e & 63;
        float v = ts[r][jc];
        bf16 h = __float2bfloat16(v);
        bf16 l = __float2bfloat16(v - __bfloat162float(h));
        size_t off = ((size_t)jb * 128 + j0l + jc) * 640 + ii0 + r;
        Abt_h[off] = h;
        Abt_l[off] = l;
    }
}

// ======================= banded A^T@V via mma ===============================
#define AVK    640
#define NCH2   (AVK / TCK)        // 20
#define ROWVB  272
#define VTILEB (32 * ROWVB)       // 8704
#define AVSTAGE (2 * TILEB + 2 * VTILEB)  // 37888

__global__ __launch_bounds__(256, 2)
void banded_av_mma(const bf16* __restrict__ Abt_h, const bf16* __restrict__ Abt_l,
                   const bf16* __restrict__ Vh, const bf16* __restrict__ Vl,
                   bf16* __restrict__ Yh, bf16* __restrict__ Yl)
{
    extern __shared__ __align__(128) char smem[];
    const uint32_t sbase = smem_u32(smem);
    const int tid = threadIdx.x;
    DECL_FRAG_IDX
    const int jb = blockIdx.y;
    const int d0 = blockIdx.x * 128;
    const int jbase = jb * 128 - 256;

    const bf16* Ab[2] = {Abt_h + (size_t)jb * 128 * 640, Abt_l + (size_t)jb * 128 * 640};
    const bf16* Vb[2] = {Vh, Vl};

    auto load_chunk = [&](int c, int st) {
        const uint32_t sb = sbase + st * AVSTAGE;
        const int k0 = c * TCK;
#pragma unroll
        for (int t = 0; t < 2; t++) {
            const bf16* base = Ab[t] + k0;
            uint32_t dstb = sb + t * TILEB;
#pragma unroll
            for (int h = 0; h < 2; h++) {
                int idx = tid + h * 256;
                int r = idx >> 2, ck = idx & 3;
                cp16(dstb + r * ROWB + ck * 16, base + (size_t)r * 640 + ck * 8);
            }
        }
#pragma unroll
        for (int t = 0; t < 2; t++) {
            const bf16* base = Vb[t] + d0;
            uint32_t dstb = sb + 2 * TILEB + t * VTILEB;
#pragma unroll
            for (int h = 0; h < 2; h++) {
                int idx = tid + h * 256;
                int r = idx >> 4, ck = idx & 15;
                int i = jbase + k0 + r;
                i = i < 0 ? 0 : (i >= N_TOK ? N_TOK - 1 : i);
                cp16(dstb + r * ROWVB + ck * 16, base + (size_t)i * D_DIM + ck * 8);
            }
        }
    };

    float acc[4][4][4];
#pragma unroll
    for (int mi = 0; mi < 4; mi++)
#pragma unroll
        for (int ni = 0; ni < 4; ni++)
#pragma unroll
            for (int q = 0; q < 4; q++) acc[mi][ni][q] = 0.f;

    load_chunk(0, 0); cp_commit();
    load_chunk(1, 1); cp_commit();

    for (int c = 0; c < NCH2; c++) {
        cp_wait<NSTAGE - 1>();
        __syncthreads();
        const uint32_t sb = sbase + (c % NSTAGE) * AVSTAGE;
#pragma unroll
        for (int s = 0; s < 2; s++) {
            const int kc = s * 16;
            uint32_t ah[4][4], al[4][4], bh[2][4], bl[2][4];
#pragma unroll
            for (int mi = 0; mi < 4; mi++) {
                uint32_t ra = (wm * 64 + mi * 16 + a_row) * ROWB + (kc + a_kg) * 2;
                ldm_x4(ah[mi][0], ah[mi][1], ah[mi][2], ah[mi][3], sb + ra);
                ldm_x4(al[mi][0], al[mi][1], al[mi][2], al[mi][3], sb + TILEB + ra);
            }
#pragma unroll
            for (int g = 0; g < 2; g++) {
                uint32_t rb = (uint32_t)(kc + (lane & 15)) * ROWVB
                            + (wn * 32 + g * 16 + (lane >> 4) * 8) * 2;
                ldm_x4t(bh[g][0], bh[g][1], bh[g][2], bh[g][3], sb + 2 * TILEB + rb);
                ldm_x4t(bl[g][0], bl[g][1], bl[g][2], bl[g][3], sb + 2 * TILEB + VTILEB + rb);
            }
#pragma unroll
            for (int mi = 0; mi < 4; mi++)
#pragma unroll
                for (int ni = 0; ni < 4; ni++) {
                    uint32_t b0h = bh[ni >> 1][(ni & 1) * 2], b1h = bh[ni >> 1][(ni & 1) * 2 + 1];
                    uint32_t b0l = bl[ni >> 1][(ni & 1) * 2], b1l = bl[ni >> 1][(ni & 1) * 2 + 1];
                    mma_bf16(acc[mi][ni], ah[mi][0], ah[mi][1], ah[mi][2], ah[mi][3], b0h, b1h);
                    mma_bf16(acc[mi][ni], ah[mi][0], ah[mi][1], ah[mi][2], ah[mi][3], b0l, b1l);
                    mma_bf16(acc[mi][ni], al[mi][0], al[mi][1], al[mi][2], al[mi][3], b0h, b1h);
                }
        }
        __syncthreads();
        if (c + NSTAGE < NCH2) load_chunk(c + NSTAGE, c % NSTAGE);
        cp_commit();
    }

    const int rbase = jb * 128 + wm * 64;
    const int cbase = d0 + wn * 32;
#pragma unroll
    for (int mi = 0; mi < 4; mi++) {
        int r0 = rbase + mi * 16 + (lane >> 2);
#pragma unroll
        for (int ni = 0; ni < 4; ni++) {
            int cc = cbase + ni * 8 + (lane & 3) * 2;
#pragma unroll
            for (int hrow = 0; hrow < 2; hrow++) {
                float v0 = acc[mi][ni][hrow * 2 + 0];
                float v1 = acc[mi][ni][hrow * 2 + 1];
                bf16 h0 = __float2bfloat16(v0);
                bf16 h1 = __float2bfloat16(v1);
                bf16 l0 = __float2bfloat16(v0 - __bfloat162float(h0));
                bf16 l1 = __float2bfloat16(v1 - __bfloat162float(h1));
                size_t off = (size_t)(r0 + hrow * 8) * D_DIM + cc;
                *(__nv_bfloat162*)(Yh + off) = __halves2bfloat162(h0, h1);
                *(__nv_bfloat162*)(Yl + off) = __halves2bfloat162(l0, l1);
            }
        }
    }
}

// ---------------------------------------------------------------------------
extern "C" void kernel_launch(void* const* d_in, const int* in_sizes, int n_in,
                              void* d_out, int out_size)
{
    const float* x  = (const float*)d_in[0];
    const float* Wq = (const float*)d_in[1];
    const float* Wk = (const float*)d_in[2];
    const float* Wv = (const float*)d_in[3];
    const float* Wo = (const float*)d_in[4];

    float *pA, *pA2, *pYd;
    cudaGetSymbolAddress((void**)&pA, g_A);
    cudaGetSymbolAddress((void**)&pA2, g_A2);
    cudaGetSymbolAddress((void**)&pYd, g_Ydump);

    bf16 *xhi, *xlo, *ph, *pl, *yh, *yl, *wsp, *abth, *abtl;
    cudaGetSymbolAddress((void**)&xhi, g_xhi);
    cudaGetSymbolAddress((void**)&xlo, g_xlo);
    cudaGetSymbolAddress((void**)&ph, g_Ph);
    cudaGetSymbolAddress((void**)&pl, g_Pl);
    cudaGetSymbolAddress((void**)&yh, g_Yh);
    cudaGetSymbolAddress((void**)&yl, g_Yl);
    cudaGetSymbolAddress((void**)&wsp, g_w);
    cudaGetSymbolAddress((void**)&abth, g_Abt_h);
    cudaGetSymbolAddress((void**)&abtl, g_Abt_l);

    const size_t WSZ = (size_t)D_DIM * D_DIM;
    const size_t NDe = (size_t)N_TOK * D_DIM;
    bf16* wq_h = wsp + 0 * WSZ; bf16* wq_l = wsp + 1 * WSZ;
    bf16* wk_h = wsp + 2 * WSZ; bf16* wk_l = wsp + 3 * WSZ;
    bf16* wv_h = wsp + 4 * WSZ; bf16* wv_l = wsp + 5 * WSZ;
    bf16* wo_h = wsp + 6 * WSZ; bf16* wo_l = wsp + 7 * WSZ;

    bf16* qh = ph + 0 * NDe; bf16* ql = pl + 0 * NDe;
    bf16* kh = ph + 1 * NDe; bf16* kl = pl + 1 * NDe;
    bf16* vh = ph + 2 * NDe; bf16* vl = pl + 2 * NDe;

    const long ND = (long)N_TOK * D_DIM;
    const long NN = (long)N_TOK * N_TOK;

    float* out = (float*)d_out;
    float* yout = out;
    float* attout = nullptr;
    if ((long)out_size >= ND + NN) {
        yout = out;
        attout = out + ND;
    } else if ((long)out_size == NN) {
        yout = pYd;
        attout = out;
    }

    const int SMEM_GEMM = NSTAGE * STAGEB;      // 81920
    const int SMEM_AV   = NSTAGE * AVSTAGE;     // 75776
    cudaFuncSetAttribute(mma_gemm_qkv, cudaFuncAttributeMaxDynamicSharedMemorySize, SMEM_GEMM);
    cudaFuncSetAttribute(mma_gemm_f32out, cudaFuncAttributeMaxDynamicSharedMemorySize, SMEM_GEMM);
    cudaFuncSetAttribute(banded_logits_mma, cudaFuncAttributeMaxDynamicSharedMemorySize, SMEM_GEMM);
    cudaFuncSetAttribute(banded_av_mma, cudaFuncAttributeMaxDynamicSharedMemorySize, SMEM_AV);

    // splits
    split_bf16<<<(N_TOK * D_DIM / 4 + 255) / 256, 256>>>(x, xhi, xlo, N_TOK * D_DIM / 4);
    split_bf16<<<(D_DIM * D_DIM / 4 + 255) / 256, 256>>>(Wq, wq_h, wq_l, D_DIM * D_DIM / 4);
    split_bf16<<<(D_DIM * D_DIM / 4 + 255) / 256, 256>>>(Wk, wk_h, wk_l, D_DIM * D_DIM / 4);
    split_bf16<<<(D_DIM * D_DIM / 4 + 255) / 256, 256>>>(Wv, wv_h, wv_l, D_DIM * D_DIM / 4);
    split_bf16<<<(D_DIM * D_DIM / 4 + 255) / 256, 256>>>(Wo, wo_h, wo_l, D_DIM * D_DIM / 4);

    // fused QKV projection (z = 0,1,2)
    mma_gemm_qkv<<<dim3(D_DIM / 128, N_TOK / 128, 3), 256, SMEM_GEMM>>>(xhi, xlo, wsp, ph, pl);

    // banded attention (split-K logits -> fused softmax/att)
    banded_logits_mma<<<dim3(5, N_TOK / 128, 2), 256, SMEM_GEMM>>>(qh, ql, kh, kl, pA, pA2);
    band_softmax_att<<<N_TOK, 256>>>(pA, pA2, attout);
    band_transpose<<<dim3(10, 2, N_TOK / 128), 256>>>(pA, abth, abtl);
    banded_av_mma<<<dim3(D_DIM / 128, N_TOK / 128), 256, SMEM_AV>>>(abth, abtl, vh, vl, yh, yl);

    // output projection
    mma_gemm_f32out<<<dim3(D_DIM / 128, N_TOK / 128), 256, SMEM_GEMM>>>(yh, yl, wo_h, wo_l, yout);
}

// round 13
// speedup vs baseline: 2.6811x; 1.0022x over previous
#include <cuda_runtime.h>
#include <cuda_bf16.h>
#include <math.h>
#include <stdint.h>

#define N_TOK 8192
#define D_DIM 1024
#define BW    512
#define BVAL  499

typedef __nv_bfloat16 bf16;

// ---------------- scratch (static device arrays, no allocation) -------------
__device__ float g_Ap[4][(size_t)N_TOK * BW];    // logits K-quarter partials
__device__ float g_Ydump[(size_t)N_TOK * D_DIM];

__device__ bf16 g_xhi[(size_t)N_TOK * D_DIM];
__device__ bf16 g_xlo[(size_t)N_TOK * D_DIM];
__device__ bf16 g_Ph[3][(size_t)N_TOK * D_DIM];   // Q,K,V hi
__device__ bf16 g_Pl[3][(size_t)N_TOK * D_DIM];   // Q,K,V lo
__device__ bf16 g_Yh[(size_t)N_TOK * D_DIM];
__device__ bf16 g_Yl[(size_t)N_TOK * D_DIM];
__device__ bf16 g_w[8][(size_t)D_DIM * D_DIM];    // qh,ql,kh,kl,vh,vl,oh,ol
__device__ bf16 g_Abt_h[(size_t)N_TOK * 640];
__device__ bf16 g_Abt_l[(size_t)N_TOK * 640];

// ======================= helpers ============================================
__device__ __forceinline__ uint32_t smem_u32(const void* p) {
    uint32_t a;
    asm("{ .reg .u64 t; cvta.to.shared.u64 t, %1; cvt.u32.u64 %0, t; }"
        : "=r"(a) : "l"(p));
    return a;
}
__device__ __forceinline__ void cp16(uint32_t dst, const void* src) {
    asm volatile("cp.async.cg.shared.global [%0], [%1], 16;" :: "r"(dst), "l"(src));
}
__device__ __forceinline__ void cp_commit() {
    asm volatile("cp.async.commit_group;" ::: "memory");
}
template <int NN_> __device__ __forceinline__ void cp_wait() {
    asm volatile("cp.async.wait_group %0;" :: "n"(NN_) : "memory");
}
__device__ __forceinline__ void ldm_x4(uint32_t& r0, uint32_t& r1, uint32_t& r2,
                                       uint32_t& r3, uint32_t addr) {
    asm volatile("ldmatrix.sync.aligned.m8n8.x4.shared.b16 {%0,%1,%2,%3}, [%4];"
                 : "=r"(r0), "=r"(r1), "=r"(r2), "=r"(r3) : "r"(addr));
}
__device__ __forceinline__ void ldm_x4t(uint32_t& r0, uint32_t& r1, uint32_t& r2,
                                        uint32_t& r3, uint32_t addr) {
    asm volatile("ldmatrix.sync.aligned.m8n8.x4.trans.shared.b16 {%0,%1,%2,%3}, [%4];"
                 : "=r"(r0), "=r"(r1), "=r"(r2), "=r"(r3) : "r"(addr));
}
__device__ __forceinline__ void mma_bf16(float* c, uint32_t a0, uint32_t a1,
                                         uint32_t a2, uint32_t a3,
                                         uint32_t b0, uint32_t b1) {
    asm volatile(
        "mma.sync.aligned.m16n8k16.row.col.f32.bf16.bf16.f32 "
        "{%0,%1,%2,%3}, {%4,%5,%6,%7}, {%8,%9}, {%0,%1,%2,%3};"
        : "+f"(c[0]), "+f"(c[1]), "+f"(c[2]), "+f"(c[3])
        : "r"(a0), "r"(a1), "r"(a2), "r"(a3), "r"(b0), "r"(b1));
}

// ======================= single fused split kernel ==========================
// region layout (float4 units): [0, 2M) = x ; then 4 x 256K for Wq,Wk,Wv,Wo
#define XF4 (N_TOK * D_DIM / 4)          // 2M
#define WF4 (D_DIM * D_DIM / 4)          // 256K
__global__ __launch_bounds__(256)
void split_all(const float* __restrict__ x,
               const float* __restrict__ wq, const float* __restrict__ wk,
               const float* __restrict__ wv, const float* __restrict__ wo,
               bf16* __restrict__ xh, bf16* __restrict__ xl,
               bf16* __restrict__ wbase)
{
    int idx = blockIdx.x * 256 + threadIdx.x;
    const float* src;
    bf16 *hi, *lo;
    int off;
    if (idx < XF4) {
        src = x; hi = xh; lo = xl; off = idx;
    } else {
        int widx = idx - XF4;
        int wsel = widx / WF4;
        off = widx - wsel * WF4;
        src = (wsel == 0) ? wq : (wsel == 1) ? wk : (wsel == 2) ? wv : wo;
        const size_t WSZ = (size_t)D_DIM * D_DIM;
        hi = wbase + (size_t)(2 * wsel) * WSZ;
        lo = wbase + (size_t)(2 * wsel + 1) * WSZ;
    }
    float4 v = ((const float4*)src)[off];
    bf16 h0 = __float2bfloat16(v.x);
    bf16 h1 = __float2bfloat16(v.y);
    bf16 h2 = __float2bfloat16(v.z);
    bf16 h3 = __float2bfloat16(v.w);
    bf16 l0 = __float2bfloat16(v.x - __bfloat162float(h0));
    bf16 l1 = __float2bfloat16(v.y - __bfloat162float(h1));
    bf16 l2 = __float2bfloat16(v.z - __bfloat162float(h2));
    bf16 l3 = __float2bfloat16(v.w - __bfloat162float(h3));
    __nv_bfloat162* hp = (__nv_bfloat162*)hi;
    __nv_bfloat162* lp = (__nv_bfloat162*)lo;
    hp[2 * off]     = __halves2bfloat162(h0, h1);
    hp[2 * off + 1] = __halves2bfloat162(h2, h3);
    lp[2 * off]     = __halves2bfloat162(l0, l1);
    lp[2 * off + 1] = __halves2bfloat162(l2, l3);
}
#define SPLIT_TOTAL (XF4 + 4 * WF4)

// ======================= GEMM tile constants ================================
#define TCK    32
#define NCH    (D_DIM / TCK)      // 32
#define ROWB   80
#define TILEB  (128 * ROWB)       // 10240
#define STAGEB (4 * TILEB)        // 40960
#define NSTAGE 2

#define DECL_FRAG_IDX                                        \
    const int lane = tid & 31;                               \
    const int wid  = tid >> 5;                               \
    const int wm   = wid & 1;                                \
    const int wn   = wid >> 1;                               \
    const int a_row = lane & 15;                             \
    const int a_kg  = (lane >> 4) * 8;                       \
    const int b_row = (lane & 7) + ((lane >> 4) << 3);       \
    const int b_kg  = ((lane >> 3) & 1) * 8;

#define GEMM_MAINLOOP(SBEXPR, NCHUNKS, LOADFN)                                 \
    load_chunk(0, 0); cp_commit();                                             \
    load_chunk(1, 1); cp_commit();                                             \
    for (int c = 0; c < (NCHUNKS); c++) {                                      \
        cp_wait<NSTAGE - 1>();                                                 \
        __syncthreads();                                                       \
        const uint32_t sb = (SBEXPR);                                          \
        _Pragma("unroll")                                                      \
        for (int s = 0; s < 2; s++) {                                          \
            const int kc = s * 16;                                             \
            uint32_t ah[4][4], al[4][4], bh[2][4], bl[2][4];                   \
            _Pragma("unroll")                                                  \
            for (int mi = 0; mi < 4; mi++) {                                   \
                uint32_t ra = (wm * 64 + mi * 16 + a_row) * ROWB + (kc + a_kg) * 2; \
                ldm_x4(ah[mi][0], ah[mi][1], ah[mi][2], ah[mi][3], sb + ra);   \
                ldm_x4(al[mi][0], al[mi][1], al[mi][2], al[mi][3], sb + TILEB + ra); \
            }                                                                  \
            _Pragma("unroll")                                                  \
            for (int g = 0; g < 2; g++) {                                      \
                uint32_t rb = (wn * 32 + g * 16 + b_row) * ROWB + (kc + b_kg) * 2; \
                ldm_x4(bh[g][0], bh[g][1], bh[g][2], bh[g][3], sb + 2 * TILEB + rb); \
                ldm_x4(bl[g][0], bl[g][1], bl[g][2], bl[g][3], sb + 3 * TILEB + rb); \
            }                                                                  \
            _Pragma("unroll")                                                  \
            for (int mi = 0; mi < 4; mi++)                                     \
                _Pragma("unroll")                                              \
                for (int ni = 0; ni < 4; ni++) {                               \
                    uint32_t b0h = bh[ni >> 1][(ni & 1) * 2], b1h = bh[ni >> 1][(ni & 1) * 2 + 1]; \
                    uint32_t b0l = bl[ni >> 1][(ni & 1) * 2], b1l = bl[ni >> 1][(ni & 1) * 2 + 1]; \
                    mma_bf16(acc[mi][ni], ah[mi][0], ah[mi][1], ah[mi][2], ah[mi][3], b0h, b1h); \
                    mma_bf16(acc[mi][ni], ah[mi][0], ah[mi][1], ah[mi][2], ah[mi][3], b0l, b1l); \
                    mma_bf16(acc[mi][ni], al[mi][0], al[mi][1], al[mi][2], al[mi][3], b0h, b1h); \
                }                                                              \
        }                                                                      \
        __syncthreads();                                                       \
        if (c + NSTAGE < (NCHUNKS)) LOADFN(c + NSTAGE, c % NSTAGE);            \
        cp_commit();                                                           \
    }

#define ZERO_ACC                                             \
    float acc[4][4][4];                                      \
    _Pragma("unroll")                                        \
    for (int mi = 0; mi < 4; mi++)                           \
        _Pragma("unroll")                                    \
        for (int ni = 0; ni < 4; ni++)                       \
            _Pragma("unroll")                                \
            for (int q = 0; q < 4; q++) acc[mi][ni][q] = 0.f;

// ======================= fused QKV projection ===============================
__global__ __launch_bounds__(256, 2)
void mma_gemm_qkv(const bf16* __restrict__ Ahi, const bf16* __restrict__ Alo,
                  const bf16* __restrict__ Wbase,
                  bf16* __restrict__ Phz, bf16* __restrict__ Plz)
{
    extern __shared__ __align__(128) char smem[];
    const uint32_t sbase = smem_u32(smem);
    const int tid = threadIdx.x;
    DECL_FRAG_IDX
    const int i0 = blockIdx.y * 128;
    const int j0 = blockIdx.x * 128;
    const int z  = blockIdx.z;
    const size_t WSZ = (size_t)D_DIM * D_DIM;
    const size_t ND  = (size_t)N_TOK * D_DIM;
    const float scale = (z == 0) ? 0.06f : 1.0f;

    const bf16* srcs[4] = {Ahi + (size_t)i0 * D_DIM, Alo + (size_t)i0 * D_DIM,
                           Wbase + 2 * z * WSZ + (size_t)j0 * D_DIM,
                           Wbase + (2 * z + 1) * WSZ + (size_t)j0 * D_DIM};
    bf16* Chi = Phz + z * ND;
    bf16* Clo = Plz + z * ND;

    auto load_chunk = [&](int c, int st) {
        const uint32_t sb = sbase + st * STAGEB;
        const int k0 = c * TCK;
#pragma unroll
        for (int t = 0; t < 4; t++) {
            const bf16* base = srcs[t] + k0;
            uint32_t dstb = sb + t * TILEB;
#pragma unroll
            for (int h = 0; h < 2; h++) {
                int idx = tid + h * 256;
                int r = idx >> 2, ck = idx & 3;
                cp16(dstb + r * ROWB + ck * 16, base + (size_t)r * D_DIM + ck * 8);
            }
        }
    };

    ZERO_ACC
    GEMM_MAINLOOP(sbase + (c % NSTAGE) * STAGEB, NCH, load_chunk)

    const int rbase = i0 + wm * 64;
    const int cbase = j0 + wn * 32;
#pragma unroll
    for (int mi = 0; mi < 4; mi++) {
        int r0 = rbase + mi * 16 + (lane >> 2);
#pragma unroll
        for (int ni = 0; ni < 4; ni++) {
            int cc = cbase + ni * 8 + (lane & 3) * 2;
#pragma unroll
            for (int hrow = 0; hrow < 2; hrow++) {
                float v0 = acc[mi][ni][hrow * 2 + 0] * scale;
                float v1 = acc[mi][ni][hrow * 2 + 1] * scale;
                bf16 h0 = __float2bfloat16(v0);
                bf16 h1 = __float2bfloat16(v1);
                bf16 l0 = __float2bfloat16(v0 - __bfloat162float(h0));
                bf16 l1 = __float2bfloat16(v1 - __bfloat162float(h1));
                size_t off = (size_t)(r0 + hrow * 8) * D_DIM + cc;
                *(__nv_bfloat162*)(Chi + off) = __halves2bfloat162(h0, h1);
                *(__nv_bfloat162*)(Clo + off) = __halves2bfloat162(l0, l1);
            }
        }
    }
}

// ======================= dense GEMM, fp32 output (final) ====================
__global__ __launch_bounds__(256, 2)
void mma_gemm_f32out(const bf16* __restrict__ Ahi, const bf16* __restrict__ Alo,
                     const bf16* __restrict__ Bhi, const bf16* __restrict__ Blo,
                     float* __restrict__ C)
{
    extern __shared__ __align__(128) char smem[];
    const uint32_t sbase = smem_u32(smem);
    const int tid = threadIdx.x;
    DECL_FRAG_IDX
    const int i0 = blockIdx.y * 128;
    const int j0 = blockIdx.x * 128;

    const bf16* srcs[4] = {Ahi + (size_t)i0 * D_DIM, Alo + (size_t)i0 * D_DIM,
                           Bhi + (size_t)j0 * D_DIM, Blo + (size_t)j0 * D_DIM};

    auto load_chunk = [&](int c, int st) {
        const uint32_t sb = sbase + st * STAGEB;
        const int k0 = c * TCK;
#pragma unroll
        for (int t = 0; t < 4; t++) {
            const bf16* base = srcs[t] + k0;
            uint32_t dstb = sb + t * TILEB;
#pragma unroll
            for (int h = 0; h < 2; h++) {
                int idx = tid + h * 256;
                int r = idx >> 2, ck = idx & 3;
                cp16(dstb + r * ROWB + ck * 16, base + (size_t)r * D_DIM + ck * 8);
            }
        }
    };

    ZERO_ACC
    GEMM_MAINLOOP(sbase + (c % NSTAGE) * STAGEB, NCH, load_chunk)

    const int rbase = i0 + wm * 64;
    const int cbase = j0 + wn * 32;
#pragma unroll
    for (int mi = 0; mi < 4; mi++) {
        int r0 = rbase + mi * 16 + (lane >> 2);
#pragma unroll
        for (int ni = 0; ni < 4; ni++) {
            int cc = cbase + ni * 8 + (lane & 3) * 2;
            *(float2*)(C + (size_t)r0 * D_DIM + cc) =
                make_float2(acc[mi][ni][0], acc[mi][ni][1]);
            *(float2*)(C + (size_t)(r0 + 8) * D_DIM + cc) =
                make_float2(acc[mi][ni][2], acc[mi][ni][3]);
        }
    }
}

// ======================= banded logits via mma (split-K x4) =================
// grid (5, 64, 4): i0 = by*128, j0 = i0 + (bx-2)*128, z = K quarter.
__global__ __launch_bounds__(256, 2)
void banded_logits_mma(const bf16* __restrict__ Qh, const bf16* __restrict__ Ql,
                       const bf16* __restrict__ Kh, const bf16* __restrict__ Kl,
                       float* __restrict__ Apart)
{
    extern __shared__ __align__(128) char smem[];
    const uint32_t sbase = smem_u32(smem);
    const int tid = threadIdx.x;
    DECL_FRAG_IDX
    const int i0 = blockIdx.y * 128;
    const int j0 = i0 + ((int)blockIdx.x - 2) * 128;
    const int kbase = blockIdx.z * (D_DIM / 4);
    float* Aout = Apart + (size_t)blockIdx.z * N_TOK * BW;

    auto load_chunk = [&](int c, int st) {
        const uint32_t sb = sbase + st * STAGEB;
        const int k0 = kbase + c * TCK;
#pragma unroll
        for (int t = 0; t < 2; t++) {
            const bf16* base = (t ? Ql : Qh) + k0;
            uint32_t dstb = sb + t * TILEB;
#pragma unroll
            for (int h = 0; h < 2; h++) {
                int idx = tid + h * 256;
                int r = idx >> 2, ck = idx & 3;
                cp16(dstb + r * ROWB + ck * 16, base + (size_t)(i0 + r) * D_DIM + ck * 8);
            }
        }
#pragma unroll
        for (int t = 0; t < 2; t++) {
            const bf16* base = (t ? Kl : Kh) + k0;
            uint32_t dstb = sb + (2 + t) * TILEB;
#pragma unroll
            for (int h = 0; h < 2; h++) {
                int idx = tid + h * 256;
                int r = idx >> 2, ck = idx & 3;
                int jr = j0 + r;
                jr = jr < 0 ? 0 : (jr >= N_TOK ? N_TOK - 1 : jr);
                cp16(dstb + r * ROWB + ck * 16, base + (size_t)jr * D_DIM + ck * 8);
            }
        }
    };

    ZERO_ACC
    GEMM_MAINLOOP(sbase + (c % NSTAGE) * STAGEB, NCH / 4, load_chunk)

    const int rbase = i0 + wm * 64;
    const int cbase = j0 + wn * 32;
#pragma unroll
    for (int mi = 0; mi < 4; mi++) {
#pragma unroll
        for (int hrow = 0; hrow < 2; hrow++) {
            int i = rbase + mi * 16 + (lane >> 2) + hrow * 8;
#pragma unroll
            for (int ni = 0; ni < 4; ni++) {
#pragma unroll
                for (int q = 0; q < 2; q++) {
                    int j = cbase + ni * 8 + (lane & 3) * 2 + q;
                    int t = j - i + 249;
                    if ((unsigned)j < (unsigned)N_TOK && (unsigned)t < (unsigned)BVAL)
                        Aout[(size_t)i * BW + t] = acc[mi][ni][hrow * 2 + q];
                }
            }
        }
    }
}

// ---- fused: sum K-quarters, band softmax, write weights + dense att row ----
__global__ __launch_bounds__(256)
void band_softmax_att(float* __restrict__ Apart, float* __restrict__ att)
{
    const int i = blockIdx.x;
    const int tlo = max(0, 249 - i);
    const int thi = min(BVAL - 1, N_TOK - 1 - i + 249);
    const int tid = threadIdx.x;
    const size_t PS = (size_t)N_TOK * BW;
    float* r0p       = Apart + (size_t)i * BW;
    const float* r1p = r0p + PS;
    const float* r2p = r0p + 2 * PS;
    const float* r3p = r0p + 3 * PS;

    __shared__ float red[256];
    __shared__ float sband[512];

    float mx = -INFINITY;
    for (int t = tlo + tid; t <= thi; t += 256) {
        float v = (r0p[t] + r1p[t]) + (r2p[t] + r3p[t]);
        sband[t] = v;
        mx = fmaxf(mx, v);
    }
    red[tid] = mx; __syncthreads();
    for (int s = 128; s > 0; s >>= 1) {
        if (tid < s) red[tid] = fmaxf(red[tid], red[tid + s]);
        __syncthreads();
    }
    mx = red[0]; __syncthreads();

    float sum = 0.f;
    for (int t = tlo + tid; t <= thi; t += 256) {
        float e = __expf(sband[t] - mx);
        sband[t] = e;
        sum += e;
    }
    red[tid] = sum; __syncthreads();
    for (int s = 128; s > 0; s >>= 1) {
        if (tid < s) red[tid] += red[tid + s];
        __syncthreads();
    }
    float inv = 1.f / red[0]; __syncthreads();

    for (int t = tlo + tid; t <= thi; t += 256) {
        float w = sband[t] * inv;
        sband[t] = w;
        r0p[t] = w;                 // normalized weights for transpose/AV
    }
    __syncthreads();

    if (att) {
        float* arow = att + (size_t)i * N_TOK;
        for (int j4 = tid * 4; j4 < N_TOK; j4 += 256 * 4) {
            float4 o;
            float r[4];
#pragma unroll
            for (int q = 0; q < 4; q++) {
                int t = j4 + q - i + 249;
                r[q] = ((unsigned)t < (unsigned)BVAL) ? sband[t] : 0.f;
            }
            o.x = r[0]; o.y = r[1]; o.z = r[2]; o.w = r[3];
            *(float4*)(arow + j4) = o;
        }
    }
}

// -------- transpose band weights into per-block K-aligned bf16 hi/lo --------
__global__ __launch_bounds__(256)
void band_transpose(const float* __restrict__ Aband,
                    bf16* __restrict__ Abt_h, bf16* __restrict__ Abt_l)
{
    const int jb = blockIdx.z;
    const int j0l = blockIdx.y * 64;
    const int ii0 = blockIdx.x * 64;
    const int j0 = jb * 128 + j0l;
    const int ibase = jb * 128 - 256 + ii0;
    const int tid = threadIdx.x;

    __shared__ float ts[64][65];

    for (int e = tid; e < 64 * 64; e += 256) {
        int r = e >> 6, jc = e & 63;
        int i = ibase + r, j = j0 + jc;
        int t = j - i + 249;
        float v = 0.f;
        if ((unsigned)i < (unsigned)N_TOK && (unsigned)t < (unsigned)BVAL)
            v = Aband[(size_t)i * BW + t];
        ts[r][jc] = v;
    }
    __syncthreads();

    for (int e = tid; e < 64 * 64; e += 256) {
        int jc = e >> 6, r = e & 63;
        float v = ts[r][jc];
        bf16 h = __float2bfloat16(v);
        bf16 l = __float2bfloat16(v - __bfloat162float(h));
        size_t off = ((size_t)jb * 128 + j0l + jc) * 640 + ii0 + r;
        Abt_h[off] = h;
        Abt_l[off] = l;
    }
}

// ======================= banded A^T@V via mma (N=64 CTA) ====================
// C[j, d] = sum_ii Abt[jb][j][ii] * V[jb*128-256+ii][d]
// CTA: 128 j-rows x 64 d-cols; 8 warps as 4(M) x 2(N), warp tile 32x32.
#define AVK     640
#define NCH2    (AVK / TCK)       // 20
#define ROWVB   144               // 64 bf16 + 16B pad
#define VTILEB  (32 * ROWVB)      // 4608
#define AVSTAGE (2 * TILEB + 2 * VTILEB)  // 29696

__global__ __launch_bounds__(256, 2)
void banded_av_mma(const bf16* __restrict__ Abt_h, const bf16* __restrict__ Abt_l,
                   const bf16* __restrict__ Vh, const bf16* __restrict__ Vl,
                   bf16* __restrict__ Yh, bf16* __restrict__ Yl)
{
    extern __shared__ __align__(128) char smem[];
    const uint32_t sbase = smem_u32(smem);
    const int tid = threadIdx.x;
    const int lane = tid & 31;
    const int wid  = tid >> 5;
    const int wm4  = wid & 3;       // M offset 32*wm4
    const int wn2  = wid >> 2;      // N offset 32*wn2
    const int a_row = lane & 15;
    const int a_kg  = (lane >> 4) * 8;
    const int jb = blockIdx.y;
    const int d0 = blockIdx.x * 64;
    const int jbase = jb * 128 - 256;

    const bf16* Ab[2] = {Abt_h + (size_t)jb * 128 * 640, Abt_l + (size_t)jb * 128 * 640};
    const bf16* Vb[2] = {Vh, Vl};

    auto load_chunk = [&](int c, int st) {
        const uint32_t sb = sbase + st * AVSTAGE;
        const int k0 = c * TCK;
#pragma unroll
        for (int t = 0; t < 2; t++) {            // A tiles: 128 rows x 32 k
            const bf16* base = Ab[t] + k0;
            uint32_t dstb = sb + t * TILEB;
#pragma unroll
            for (int h = 0; h < 2; h++) {
                int idx = tid + h * 256;
                int r = idx >> 2, ck = idx & 3;
                cp16(dstb + r * ROWB + ck * 16, base + (size_t)r * 640 + ck * 8);
            }
        }
#pragma unroll
        for (int t = 0; t < 2; t++) {            // V tiles: 32 i-rows x 64 d
            const bf16* base = Vb[t] + d0;
            uint32_t dstb = sb + 2 * TILEB + t * VTILEB;
            {
                int r = tid >> 3, ck = tid & 7;  // 32 rows x 8 ck = 256
                int i = jbase + k0 + r;
                i = i < 0 ? 0 : (i >= N_TOK ? N_TOK - 1 : i);
                cp16(dstb + r * ROWVB + ck * 16, base + (size_t)i * D_DIM + ck * 8);
            }
        }
    };

    float acc[2][4][4];
#pragma unroll
    for (int mi = 0; mi < 2; mi++)
#pragma unroll
        for (int ni = 0; ni < 4; ni++)
#pragma unroll
            for (int q = 0; q < 4; q++) acc[mi][ni][q] = 0.f;

    load_chunk(0, 0); cp_commit();
    load_chunk(1, 1); cp_commit();

    for (int c = 0; c < NCH2; c++) {
        cp_wait<NSTAGE - 1>();
        __syncthreads();
        const uint32_t sb = sbase + (c % NSTAGE) * AVSTAGE;
#pragma unroll
        for (int s = 0; s < 2; s++) {
            const int kc = s * 16;
            uint32_t ah[2][4], al[2][4], bh[2][4], bl[2][4];
#pragma unroll
            for (int mi = 0; mi < 2; mi++) {
                uint32_t ra = (wm4 * 32 + mi * 16 + a_row) * ROWB + (kc + a_kg) * 2;
                ldm_x4(ah[mi][0], ah[mi][1], ah[mi][2], ah[mi][3], sb + ra);
                ldm_x4(al[mi][0], al[mi][1], al[mi][2], al[mi][3], sb + TILEB + ra);
            }
#pragma unroll
            for (int g = 0; g < 2; g++) {
                uint32_t rb = (uint32_t)(kc + (lane & 15)) * ROWVB
                            + (wn2 * 32 + g * 16 + (lane >> 4) * 8) * 2;
                ldm_x4t(bh[g][0], bh[g][1], bh[g][2], bh[g][3], sb + 2 * TILEB + rb);
                ldm_x4t(bl[g][0], bl[g][1], bl[g][2], bl[g][3], sb + 2 * TILEB + VTILEB + rb);
            }
#pragma unroll
            for (int mi = 0; mi < 2; mi++)
#pragma unroll
                for (int ni = 0; ni < 4; ni++) {
                    uint32_t b0h = bh[ni >> 1][(ni & 1) * 2], b1h = bh[ni >> 1][(ni & 1) * 2 + 1];
                    uint32_t b0l = bl[ni >> 1][(ni & 1) * 2], b1l = bl[ni >> 1][(ni & 1) * 2 + 1];
                    mma_bf16(acc[mi][ni], ah[mi][0], ah[mi][1], ah[mi][2], ah[mi][3], b0h, b1h);
                    mma_bf16(acc[mi][ni], ah[mi][0], ah[mi][1], ah[mi][2], ah[mi][3], b0l, b1l);
                    mma_bf16(acc[mi][ni], al[mi][0], al[mi][1], al[mi][2], al[mi][3], b0h, b1h);
                }
        }
        __syncthreads();
        if (c + NSTAGE < NCH2) load_chunk(c + NSTAGE, c % NSTAGE);
        cp_commit();
    }

    const int rbase = jb * 128 + wm4 * 32;
    const int cbase = d0 + wn2 * 32;
#pragma unroll
    for (int mi = 0; mi < 2; mi++) {
        int r0 = rbase + mi * 16 + (lane >> 2);
#pragma unroll
        for (int ni = 0; ni < 4; ni++) {
            int cc = cbase + ni * 8 + (lane & 3) * 2;
#pragma unroll
            for (int hrow = 0; hrow < 2; hrow++) {
                float v0 = acc[mi][ni][hrow * 2 + 0];
                float v1 = acc[mi][ni][hrow * 2 + 1];
                bf16 h0 = __float2bfloat16(v0);
                bf16 h1 = __float2bfloat16(v1);
                bf16 l0 = __float2bfloat16(v0 - __bfloat162float(h0));
                bf16 l1 = __float2bfloat16(v1 - __bfloat162float(h1));
                size_t off = (size_t)(r0 + hrow * 8) * D_DIM + cc;
                *(__nv_bfloat162*)(Yh + off) = __halves2bfloat162(h0, h1);
                *(__nv_bfloat162*)(Yl + off) = __halves2bfloat162(l0, l1);
            }
        }
    }
}

// ---------------------------------------------------------------------------
extern "C" void kernel_launch(void* const* d_in, const int* in_sizes, int n_in,
                              void* d_out, int out_size)
{
    const float* x  = (const float*)d_in[0];
    const float* Wq = (const float*)d_in[1];
    const float* Wk = (const float*)d_in[2];
    const float* Wv = (const float*)d_in[3];
    const float* Wo = (const float*)d_in[4];

    float *pAp, *pYd;
    cudaGetSymbolAddress((void**)&pAp, g_Ap);
    cudaGetSymbolAddress((void**)&pYd, g_Ydump);

    bf16 *xhi, *xlo, *ph, *pl, *yh, *yl, *wsp, *abth, *abtl;
    cudaGetSymbolAddress((void**)&xhi, g_xhi);
    cudaGetSymbolAddress((void**)&xlo, g_xlo);
    cudaGetSymbolAddress((void**)&ph, g_Ph);
    cudaGetSymbolAddress((void**)&pl, g_Pl);
    cudaGetSymbolAddress((void**)&yh, g_Yh);
    cudaGetSymbolAddress((void**)&yl, g_Yl);
    cudaGetSymbolAddress((void**)&wsp, g_w);
    cudaGetSymbolAddress((void**)&abth, g_Abt_h);
    cudaGetSymbolAddress((void**)&abtl, g_Abt_l);

    const size_t WSZ = (size_t)D_DIM * D_DIM;
    const size_t NDe = (size_t)N_TOK * D_DIM;
    bf16* wo_h = wsp + 6 * WSZ; bf16* wo_l = wsp + 7 * WSZ;

    bf16* qh = ph + 0 * NDe; bf16* ql = pl + 0 * NDe;
    bf16* kh = ph + 1 * NDe; bf16* kl = pl + 1 * NDe;
    bf16* vh = ph + 2 * NDe; bf16* vl = pl + 2 * NDe;

    const long ND = (long)N_TOK * D_DIM;
    const long NN = (long)N_TOK * N_TOK;

    float* out = (float*)d_out;
    float* yout = out;
    float* attout = nullptr;
    if ((long)out_size >= ND + NN) {
        yout = out;
        attout = out + ND;
    } else if ((long)out_size == NN) {
        yout = pYd;
        attout = out;
    }

    const int SMEM_GEMM = NSTAGE * STAGEB;      // 81920
    const int SMEM_AV   = NSTAGE * AVSTAGE;     // 59392
    cudaFuncSetAttribute(mma_gemm_qkv, cudaFuncAttributeMaxDynamicSharedMemorySize, SMEM_GEMM);
    cudaFuncSetAttribute(mma_gemm_f32out, cudaFuncAttributeMaxDynamicSharedMemorySize, SMEM_GEMM);
    cudaFuncSetAttribute(banded_logits_mma, cudaFuncAttributeMaxDynamicSharedMemorySize, SMEM_GEMM);
    cudaFuncSetAttribute(banded_av_mma, cudaFuncAttributeMaxDynamicSharedMemorySize, SMEM_AV);

    // single fused split launch (x + 4 weights)
    split_all<<<(SPLIT_TOTAL + 255) / 256, 256>>>(x, Wq, Wk, Wv, Wo, xhi, xlo, wsp);

    // fused QKV projection (z = 0,1,2)
    mma_gemm_qkv<<<dim3(D_DIM / 128, N_TOK / 128, 3), 256, SMEM_GEMM>>>(xhi, xlo, wsp, ph, pl);

    // banded attention (split-K x4 logits -> fused softmax/att)
    banded_logits_mma<<<dim3(5, N_TOK / 128, 4), 256, SMEM_GEMM>>>(qh, ql, kh, kl, pAp);
    band_softmax_att<<<N_TOK, 256>>>(pAp, attout);
    band_transpose<<<dim3(10, 2, N_TOK / 128), 256>>>(pAp, abth, abtl);
    banded_av_mma<<<dim3(D_DIM / 64, N_TOK / 128), 256, SMEM_AV>>>(abth, abtl, vh, vl, yh, yl);

    // output projection
    mma_gemm_f32out<<<dim3(D_DIM / 128, N_TOK / 128), 256, SMEM_GEMM>>>(yh, yl, wo_h, wo_l, yout);
}